// round 12
// baseline (speedup 1.0000x reference)
#include <cuda_runtime.h>
#include <cuda_bf16.h>
#include <math.h>

#define Bv 2
#define Cv 64
#define Hv 80
#define Wv 80
#define Nv 6400
#define NQ 1600
#define NHWf 12800.0f
#define EPSV 1e-5f
#define L2E 1.44269504088896f

typedef unsigned long long ull;

// ---------------- packed helpers ----------------
__device__ __forceinline__ ull pk2(float lo, float hi) {
    ull r; asm("mov.b64 %0,{%1,%2};" : "=l"(r) : "f"(lo), "f"(hi)); return r;
}
__device__ __forceinline__ void upk2(ull v, float& lo, float& hi) {
    asm("mov.b64 {%0,%1},%2;" : "=f"(lo), "=f"(hi) : "l"(v));
}
__device__ __forceinline__ ull fma2_(ull a, ull b, ull c) {
    ull d; asm("fma.rn.f32x2 %0,%1,%2,%3;" : "=l"(d) : "l"(a), "l"(b), "l"(c)); return d;
}
__device__ __forceinline__ float ex2_(float x) {
    float y; asm("ex2.approx.ftz.f32 %0,%1;" : "=f"(y) : "f"(x)); return y;
}
__device__ __forceinline__ unsigned pkbf(float lo, float hi) {
    unsigned d; asm("cvt.rn.bf16x2.f32 %0,%1,%2;" : "=r"(d) : "f"(hi), "f"(lo)); return d;
}
__device__ __forceinline__ void mma16816(float* c, unsigned a0, unsigned a1, unsigned a2,
                                         unsigned a3, unsigned b0, unsigned b1) {
    asm("mma.sync.aligned.m16n8k16.row.col.f32.bf16.bf16.f32 "
        "{%0,%1,%2,%3},{%4,%5,%6,%7},{%8,%9},{%0,%1,%2,%3};"
        : "+f"(c[0]), "+f"(c[1]), "+f"(c[2]), "+f"(c[3])
        : "r"(a0), "r"(a1), "r"(a2), "r"(a3), "r"(b0), "r"(b1));
}

// ---------------- scratch ----------------
#define OFF_T0     0
#define OFF_T0T    (OFF_T0   + Bv*Cv*Nv)   /* [b][n][c] transposed */
#define OFF_T1     (OFF_T0T  + Bv*Cv*Nv)
#define OFF_VBT    (OFF_T1   + Bv*Cv*Nv)   /* [b][n][c] */
#define OFF_SAB    (OFF_VBT  + Bv*Cv*Nv)
#define OFF_SCB    (OFF_SAB  + Bv*Cv*Nv)
#define OFF_QB     (OFF_SCB  + Bv*Cv*Nv)
#define OFF_KB     (OFF_QB   + Bv*Cv*NQ)
#define OFF_ATTN   (OFF_KB   + Bv*Cv*NQ)
#define OFF_PS     (OFF_ATTN + Bv*Cv*Cv)
#define OFF_PSS    (OFF_PS   + 64*64)
#define OFF_SC1    (OFF_PSS  + 64*64)
#define OFF_SH1    (OFF_SC1  + 64)
#define OFF_QG     (OFF_SH1  + 64)          /* bf16 [B][N][16] */
#define OFF_KG     (OFF_QG   + Bv*Nv*8)
#define OFF_VG     (OFF_KG   + Bv*Nv*8)     /* bf16 [B][C][N] */
#define BUF_TOTAL  (OFF_VG   + Bv*Cv*Nv/2)

__device__ __align__(16) float g_buf[BUF_TOTAL];

// ---------------- conv3x3 (pad=1, no bias) + fused per-block BN stats ------------------
// grid (5,5, B*4), block (16,8) — each thread computes 2 pixels (rows ty, ty+8) x 16 co.
// AFFINE: compute input BN affine in-kernel from psIn/pssIn (2 slots) + g/bb.
template <int AFFINE, int WRITET>
__global__ void conv3x3_kernel(const float* __restrict__ in, const float* __restrict__ w,
                               const float* __restrict__ psIn, const float* __restrict__ pssIn,
                               const float* __restrict__ bng, const float* __restrict__ bnb,
                               float* __restrict__ out, float* __restrict__ outT,
                               float* __restrict__ ps, float* __restrict__ pss) {
    extern __shared__ float sm[];
    float* tile = sm;                                   // 32*324
    ull* w2 = (ull*)(sm + 32 * 324);                    // [ci*9+tap][8] co-pairs (all 64 ci)
    __shared__ float aff[128];
    __shared__ float red[4][32];
    int bz = blockIdx.z;
    int b = bz >> 2, co0 = (bz & 3) * 16;
    int t = threadIdx.y * 16 + threadIdx.x;             // 0..127

    float* wflat = (float*)w2;
    for (int i = t; i < 9216; i += 128) {
        int co = i & 15, r = i >> 4;
        wflat[r * 16 + co] = w[(co0 + co) * 576 + r];
    }
    if (AFFINE && t < 64) {
        float s = psIn[t * 64] + psIn[t * 64 + 1];
        float ss = pssIn[t * 64] + pssIn[t * 64 + 1];
        float m = s / NHWf;
        float var = ss / NHWf - m * m;
        float rs = rsqrtf(var + EPSV);
        float sc = bng[t] * rs;
        aff[t] = sc;
        aff[64 + t] = bnb[t] - m * sc;
    }

    int oy0 = blockIdx.y * 16, ox0 = blockIdx.x * 16;
    const float* inb = in + (long)b * Cv * Nv;

    ull acc0[8], acc1[8];
#pragma unroll
    for (int c2 = 0; c2 < 8; c2++) { acc0[c2] = pk2(0.f, 0.f); acc1[c2] = pk2(0.f, 0.f); }

    for (int chunk = 0; chunk < 2; chunk++) {
        int cbase = chunk * 32;
        __syncthreads();
        for (int i = t; i < 32 * 324; i += 128) {
            int ci = i / 324;
            int pos = i - ci * 324;
            int r = pos / 18, c2 = pos - r * 18;
            int gy = oy0 + r - 1, gx = ox0 + c2 - 1;
            float v = 0.f;
            if (gy >= 0 && gy < Hv && gx >= 0 && gx < Wv) {
                v = inb[(cbase + ci) * Nv + gy * Wv + gx];
                if (AFFINE) v = v * aff[cbase + ci] + aff[64 + cbase + ci];
            }
            tile[i] = v;
        }
        __syncthreads();

        for (int ci = 0; ci < 32; ci++) {
            const float* tp0 = tile + ci * 324 + threadIdx.y * 18 + threadIdx.x;
            const float* tp1 = tp0 + 8 * 18;
            float x0[9], x1[9];
#pragma unroll
            for (int ky = 0; ky < 3; ky++)
#pragma unroll
                for (int kx = 0; kx < 3; kx++) {
                    x0[ky * 3 + kx] = tp0[ky * 18 + kx];
                    x1[ky * 3 + kx] = tp1[ky * 18 + kx];
                }
            const ull* wr = w2 + (long)(cbase + ci) * 72;
#pragma unroll
            for (int tap = 0; tap < 9; tap++) {
                ull xd0 = pk2(x0[tap], x0[tap]);
                ull xd1 = pk2(x1[tap], x1[tap]);
#pragma unroll
                for (int c2 = 0; c2 < 8; c2++) {
                    ull wv = wr[tap * 8 + c2];
                    acc0[c2] = fma2_(xd0, wv, acc0[c2]);
                    acc1[c2] = fma2_(xd1, wv, acc1[c2]);
                }
            }
        }
    }
    int pix0 = (oy0 + threadIdx.y) * Wv + ox0 + threadIdx.x;
    int pix1 = pix0 + 8 * Wv;
    long ob0 = ((long)b * 64 + co0) * Nv + pix0;
    long ob1 = ((long)b * 64 + co0) * Nv + pix1;
    float v[16], q[16], va[16], vb2[16];
#pragma unroll
    for (int c2 = 0; c2 < 8; c2++) {
        float lo0, hi0, lo1, hi1;
        upk2(acc0[c2], lo0, hi0);
        upk2(acc1[c2], lo1, hi1);
        out[ob0 + (long)(2 * c2) * Nv] = lo0;
        out[ob0 + (long)(2 * c2 + 1) * Nv] = hi0;
        out[ob1 + (long)(2 * c2) * Nv] = lo1;
        out[ob1 + (long)(2 * c2 + 1) * Nv] = hi1;
        va[2 * c2] = lo0; va[2 * c2 + 1] = hi0;
        vb2[2 * c2] = lo1; vb2[2 * c2 + 1] = hi1;
        v[2 * c2] = lo0 + lo1; v[2 * c2 + 1] = hi0 + hi1;
        q[2 * c2] = lo0 * lo0 + lo1 * lo1; q[2 * c2 + 1] = hi0 * hi0 + hi1 * hi1;
    }
    if (WRITET) {
        float4* t0p = (float4*)(outT + ((long)b * Nv + pix0) * 64 + co0);
        float4* t1p = (float4*)(outT + ((long)b * Nv + pix1) * 64 + co0);
#pragma unroll
        for (int c4 = 0; c4 < 4; c4++) {
            t0p[c4] = make_float4(va[4 * c4], va[4 * c4 + 1], va[4 * c4 + 2], va[4 * c4 + 3]);
            t1p[c4] = make_float4(vb2[4 * c4], vb2[4 * c4 + 1], vb2[4 * c4 + 2], vb2[4 * c4 + 3]);
        }
    }
#pragma unroll
    for (int c = 0; c < 16; c++) {
#pragma unroll
        for (int off = 16; off > 0; off >>= 1) {
            v[c] += __shfl_xor_sync(0xffffffffu, v[c], off);
            q[c] += __shfl_xor_sync(0xffffffffu, q[c], off);
        }
    }
    int warp = t >> 5, lane = t & 31;
    if (lane < 16) red[warp][lane] = v[lane];
    else red[warp][lane] = q[lane - 16];
    __syncthreads();
    if (t < 32) {
        float s = 0.f;
#pragma unroll
        for (int wi = 0; wi < 4; wi++) s += red[wi][t];
        int slot = b * 25 + blockIdx.y * 5 + blockIdx.x;
        if (t < 16) ps[(co0 + t) * 64 + slot] = s;
        else pss[(co0 + t - 16) * 64 + slot] = s;
    }
}

// ---------------- BN finalize (BN1 only) ----------------
__global__ void bn_finalize(const float* __restrict__ ps, const float* __restrict__ pss,
                            const float* __restrict__ g, const float* __restrict__ bb,
                            float* __restrict__ scale, float* __restrict__ shift, int nslots) {
    int c = threadIdx.x;
    float s = 0.f, ss = 0.f;
    for (int i = 0; i < nslots; i++) { s += ps[c * 64 + i]; ss += pss[c * 64 + i]; }
    float m = s / NHWf;
    float var = ss / NHWf - m * m;
    float rs = rsqrtf(var + EPSV);
    float sc = g[c] * rs;
    scale[c] = sc;
    shift[c] = bb[c] - m * sc;
}

// ---------------- final BN apply (+relu) with inline finalize (50 slots) ----------------
__global__ void bn_apply_kernel(const float4* __restrict__ in, float4* __restrict__ out,
                                const float* __restrict__ ps, const float* __restrict__ pss,
                                const float* __restrict__ g, const float* __restrict__ bb) {
    __shared__ float scs[64], shs[64];
    int t = threadIdx.x;
    if (t < 64) {
        float s = 0.f, ss = 0.f;
#pragma unroll 5
        for (int i = 0; i < 50; i++) { s += ps[t * 64 + i]; ss += pss[t * 64 + i]; }
        float m = s / NHWf;
        float var = ss / NHWf - m * m;
        float rs = rsqrtf(var + EPSV);
        float sc = g[t] * rs;
        scs[t] = sc;
        shs[t] = bb[t] - m * sc;
    }
    __syncthreads();
    int i = blockIdx.x * 256 + t;
    int c = (i / 1600) & 63;
    float sc = scs[c], sh = shs[c];
    float4 v = in[i];
    v.x = fmaxf(v.x * sc + sh, 0.f);
    v.y = fmaxf(v.y * sc + sh, 0.f);
    v.z = fmaxf(v.z * sc + sh, 0.f);
    v.w = fmaxf(v.w * sc + sh, 0.f);
    out[i] = v;
}

// ---------------- BN apply in-place on [n][c] layout (+relu) ----------------
__global__ void bn_applyT_kernel(float4* __restrict__ buf,
                                 const float4* __restrict__ sc4,
                                 const float4* __restrict__ sh4) {
    int i = blockIdx.x * 256 + threadIdx.x;
    int cg = i & 15;
    float4 sc = sc4[cg], sh = sh4[cg];
    float4 v = buf[i];
    v.x = fmaxf(v.x * sc.x + sh.x, 0.f);
    v.y = fmaxf(v.y * sc.y + sh.y, 0.f);
    v.z = fmaxf(v.z * sc.z + sh.z, 0.f);
    v.w = fmaxf(v.w * sc.w + sh.w, 0.f);
    buf[i] = v;
}

// ---------------- fused conv2x2 stride2: q AND k in one block (8 co each) ---------------
// grid (13, 8, B), block 128. Input read ONCE for both convs.
__global__ void convqk_kernel(const float* __restrict__ f1T,
                              const float* __restrict__ wq, const float* __restrict__ bq,
                              const float* __restrict__ wk, const float* __restrict__ bk,
                              float* __restrict__ outq, float* __restrict__ outk) {
    __shared__ __align__(16) float wsmq[2048];  // [(ci*4+tap)*8+co]
    __shared__ __align__(16) float wsmk[2048];
    int co0 = blockIdx.y * 8;
    int b = blockIdx.z;

    for (int i = threadIdx.x; i < 2048; i += 128) {
        int co = i & 7, r = i >> 3;
        wsmq[r * 8 + co] = wq[(co0 + co) * 256 + r];
        wsmk[r * 8 + co] = wk[(co0 + co) * 256 + r];
    }
    __syncthreads();

    int p = blockIdx.x * 128 + threadIdx.x;
    if (p >= NQ) return;
    int oy = p / 40, ox = p % 40;
    const float* f1b = f1T + (long)b * Nv * 64;
    const float4* p00 = (const float4*)(f1b + ((2 * oy) * Wv + 2 * ox) * 64);
    const float4* p01 = p00 + 16;
    const float4* p10 = (const float4*)(f1b + ((2 * oy + 1) * Wv + 2 * ox) * 64);
    const float4* p11 = p10 + 16;

    ull aq[4], ak[4];
    const ull* w2q = (const ull*)wsmq;
    const ull* w2k = (const ull*)wsmk;
#pragma unroll
    for (int c2 = 0; c2 < 4; c2++) {
        aq[c2] = pk2(bq[co0 + 2 * c2], bq[co0 + 2 * c2 + 1]);
        ak[c2] = pk2(bk[co0 + 2 * c2], bk[co0 + 2 * c2 + 1]);
    }

#pragma unroll 2
    for (int ci4 = 0; ci4 < 16; ci4++) {
        float a0[4], a1[4], a2[4], a3[4];
        *(float4*)a0 = p00[ci4];
        *(float4*)a1 = p01[ci4];
        *(float4*)a2 = p10[ci4];
        *(float4*)a3 = p11[ci4];
#pragma unroll
        for (int j = 0; j < 4; j++) {
            ull x0 = pk2(a0[j], a0[j]), x1 = pk2(a1[j], a1[j]);
            ull x2 = pk2(a2[j], a2[j]), x3 = pk2(a3[j], a3[j]);
            int ci = ci4 * 4 + j;
            const ull* wrq = w2q + ci * 16;   // 4 taps * 4 ull
            const ull* wrk = w2k + ci * 16;
#pragma unroll
            for (int c2 = 0; c2 < 4; c2++) {
                ull a = fma2_(x0, wrq[c2], aq[c2]);
                a = fma2_(x1, wrq[4 + c2], a);
                a = fma2_(x2, wrq[8 + c2], a);
                aq[c2] = fma2_(x3, wrq[12 + c2], a);
                ull e = fma2_(x0, wrk[c2], ak[c2]);
                e = fma2_(x1, wrk[4 + c2], e);
                e = fma2_(x2, wrk[8 + c2], e);
                ak[c2] = fma2_(x3, wrk[12 + c2], e);
            }
        }
    }
    long obase = ((long)b * 64 + co0) * NQ + p;
#pragma unroll
    for (int c2 = 0; c2 < 4; c2++) {
        float lo, hi;
        upk2(aq[c2], lo, hi);
        outq[obase + (long)(2 * c2) * NQ] = lo;
        outq[obase + (long)(2 * c2 + 1) * NQ] = hi;
        upk2(ak[c2], lo, hi);
        outk[obase + (long)(2 * c2) * NQ] = lo;
        outk[obase + (long)(2 * c2 + 1) * NQ] = hi;
    }
}

// ---------------- pq/pk 1x1 conv (8 outs), [n][c] input, bf16 [n][16] out ---------------
__global__ void convqk1x1_kernel(const float* __restrict__ f1T,
                                 const float* __restrict__ wq, const float* __restrict__ bq,
                                 const float* __restrict__ wk, const float* __restrict__ bk,
                                 __nv_bfloat16* __restrict__ qg, __nv_bfloat16* __restrict__ kg) {
    __shared__ __align__(16) float wsm[512];  // [ci*8+co]
    int b = blockIdx.x;
    int which = blockIdx.z;
    const float* w = which ? wk : wq;
    const float* bias = which ? bk : bq;
    __nv_bfloat16* outg = which ? kg : qg;
    float osc = which ? 1.f : L2E;
    int n = blockIdx.y * 128 + threadIdx.x;
    for (int i = threadIdx.x; i < 512; i += 128) {
        int co = i >> 6, ci = i & 63;
        wsm[ci * 8 + co] = w[i];
    }
    __syncthreads();
    float aq[8];
#pragma unroll
    for (int j = 0; j < 8; j++) aq[j] = bias[j];
    const float4* inp = (const float4*)(f1T + ((long)b * Nv + n) * 64);
    const float4* w4p = (const float4*)wsm;
#pragma unroll 4
    for (int ci4 = 0; ci4 < 16; ci4++) {
        float va[4];
        *(float4*)va = inp[ci4];
#pragma unroll
        for (int j = 0; j < 4; j++) {
            float xv = va[j];
            int ci = ci4 * 4 + j;
#pragma unroll
            for (int c4 = 0; c4 < 2; c4++) {
                float4 w4 = w4p[ci * 2 + c4];
                aq[c4 * 4 + 0] += w4.x * xv; aq[c4 * 4 + 1] += w4.y * xv;
                aq[c4 * 4 + 2] += w4.z * xv; aq[c4 * 4 + 3] += w4.w * xv;
            }
        }
    }
    uint4* qd = (uint4*)(outg + ((long)b * Nv + n) * 16);
    qd[0] = make_uint4(pkbf(aq[0] * osc, aq[1] * osc), pkbf(aq[2] * osc, aq[3] * osc),
                       pkbf(aq[4] * osc, aq[5] * osc), pkbf(aq[6] * osc, aq[7] * osc));
    qd[1] = make_uint4(0u, 0u, 0u, 0u);
}

// ---------------- conv1x1 from [n][c] input, 16-co groups ------------------------------
// OUTMODE: 0 = f32 [c][n], 1 = f32 [n][c], 2 = bf16 [c][n]
template <int OUTMODE, int PERBATCH, int HASBIAS>
__global__ void conv1x1T_kernel(const float* __restrict__ inT, const float* __restrict__ w,
                                const float* __restrict__ bias, void* __restrict__ out) {
    __shared__ __align__(16) float wsm[1024];
    int b = blockIdx.x;
    int co0 = blockIdx.z * 16;
    int n = blockIdx.y * 128 + threadIdx.x;
    const float* wb = w + (PERBATCH ? (long)b * 4096 : 0);
    for (int i = threadIdx.x; i < 1024; i += 128) {
        int co = i >> 6, ci = i & 63;
        wsm[ci * 16 + co] = wb[(co0 + co) * 64 + ci];
    }
    __syncthreads();
    float acc[16];
#pragma unroll
    for (int co = 0; co < 16; co++) acc[co] = HASBIAS ? bias[co0 + co] : 0.f;
    const float4* inp = (const float4*)(inT + ((long)b * Nv + n) * 64);
    const float4* wsm4 = (const float4*)wsm;
#pragma unroll 4
    for (int ci4 = 0; ci4 < 16; ci4++) {
        float va[4];
        *(float4*)va = inp[ci4];
#pragma unroll
        for (int j = 0; j < 4; j++) {
            float xv = va[j];
#pragma unroll
            for (int c4 = 0; c4 < 4; c4++) {
                float4 w4 = wsm4[(ci4 * 4 + j) * 4 + c4];
                acc[c4 * 4 + 0] += w4.x * xv;
                acc[c4 * 4 + 1] += w4.y * xv;
                acc[c4 * 4 + 2] += w4.z * xv;
                acc[c4 * 4 + 3] += w4.w * xv;
            }
        }
    }
    if (OUTMODE == 1) {
        float4* ob = (float4*)((float*)out + ((long)b * Nv + n) * 64 + co0);
#pragma unroll
        for (int c4 = 0; c4 < 4; c4++)
            ob[c4] = make_float4(acc[4 * c4], acc[4 * c4 + 1], acc[4 * c4 + 2], acc[4 * c4 + 3]);
    } else if (OUTMODE == 2) {
        __nv_bfloat16* ob = (__nv_bfloat16*)out + ((long)b * 64 + co0) * Nv + n;
#pragma unroll
        for (int co = 0; co < 16; co++) ob[(long)co * Nv] = __float2bfloat16(acc[co]);
    } else {
        float* ob = (float*)out + ((long)b * 64 + co0) * Nv + n;
#pragma unroll
        for (int co = 0; co < 16; co++) ob[(long)co * Nv] = acc[co];
    }
}

// ---------------- CAM energy + softmax, 256 threads (4 slices x 64 rows) ----------------
__global__ void cam_kernel(const float* __restrict__ q, const float* __restrict__ k,
                           float* __restrict__ attn) {
    __shared__ __align__(16) float qsm[NQ];
    __shared__ float part[256];
    __shared__ float er[64];
    __shared__ float pe[64];
    int b = blockIdx.x >> 6, c = blockIdx.x & 63;
    const float* qr = q + (long)(b * 64 + c) * NQ;
    for (int i = threadIdx.x; i < 400; i += 256)
        ((float4*)qsm)[i] = ((const float4*)qr)[i];
    __syncthreads();
    int d = threadIdx.x & 63;
    int slice = threadIdx.x >> 6;  // 0..3, 100 float4 each
    const float4* kr = (const float4*)(k + (long)(b * 64 + d) * NQ) + slice * 100;
    const float4* q4 = (const float4*)qsm + slice * 100;
    float s = 0.f;
#pragma unroll 4
    for (int i = 0; i < 100; i++) {
        float4 kv = kr[i];
        float4 qv = q4[i];
        s += qv.x * kv.x + qv.y * kv.y + qv.z * kv.z + qv.w * kv.w;
    }
    part[slice * 64 + d] = s;
    __syncthreads();
    if (threadIdx.x < 64) {
        int dd = threadIdx.x;
        float e = part[dd] + part[64 + dd] + part[128 + dd] + part[192 + dd];
        er[dd] = e;
    }
    __syncthreads();
    if (threadIdx.x < 64) {
        int dd = threadIdx.x;
        float e = er[dd];
        float mn = er[0];
        for (int i = 1; i < 64; i++) mn = fminf(mn, er[i]);
        pe[dd] = __expf(mn - e);
    }
    __syncthreads();
    if (threadIdx.x < 64) {
        int dd = threadIdx.x;
        float sum = 0.f;
        for (int i = 0; i < 64; i++) sum += pe[i];
        attn[(long)(b * 64 + c) * 64 + dd] = pe[dd] / sum;
    }
}

// ---------------- PAM: flash attention via mma.sync bf16, 128-key tiles ----------------
__global__ void __launch_bounds__(128) pam_mma_kernel(
    const __nv_bfloat16* __restrict__ qg, const __nv_bfloat16* __restrict__ kg,
    const __nv_bfloat16* __restrict__ vg, float* __restrict__ sc) {
    __shared__ __align__(16) __nv_bfloat16 Qs[64 * 16];
    __shared__ __align__(16) __nv_bfloat16 Ks[128 * 16];
    __shared__ __align__(16) __nv_bfloat16 Vs[64 * 136];
    int b = blockIdx.y;
    int q0 = blockIdx.x * 64;
    int t = threadIdx.x, w = t >> 5, lane = t & 31;
    int g = lane >> 2, ti = lane & 3;

    ((uint4*)Qs)[t] = ((const uint4*)(qg + ((long)b * Nv + q0) * 16))[t];
    __syncthreads();

    unsigned qa0, qa1, qa2, qa3;
    {
        const unsigned* qw = (const unsigned*)Qs;
        int r = w * 16 + g;
        qa0 = qw[r * 8 + ti];
        qa1 = qw[(r + 8) * 8 + ti];
        qa2 = qw[r * 8 + ti + 4];
        qa3 = qw[(r + 8) * 8 + ti + 4];
    }

    float o[8][4];
#pragma unroll
    for (int nc = 0; nc < 8; nc++) { o[nc][0] = o[nc][1] = o[nc][2] = o[nc][3] = 0.f; }
    float li_lo = 0.f, li_hi = 0.f, mi_lo = -1e30f, mi_hi = -1e30f;

    for (int j0 = 0; j0 < Nv; j0 += 128) {
        __syncthreads();
        {
            const uint4* src = (const uint4*)(kg + ((long)b * Nv + j0) * 16);
            ((uint4*)Ks)[t] = src[t];
            ((uint4*)Ks)[t + 128] = src[t + 128];
        }
#pragma unroll
        for (int i = t; i < 1024; i += 128) {
            int c = i >> 4, h = i & 15;
            *(uint4*)(Vs + c * 136 + h * 8) =
                *(const uint4*)(vg + ((long)(b * 64 + c)) * Nv + j0 + h * 8);
        }
        __syncthreads();

#pragma unroll
        for (int sub = 0; sub < 2; sub++) {
            float s[8][4];
            const unsigned* kw = (const unsigned*)Ks + sub * 512;
#pragma unroll
            for (int nt = 0; nt < 8; nt++) {
                int j = nt * 8 + g;
                unsigned b0 = kw[j * 8 + ti];
                unsigned b1 = kw[j * 8 + ti + 4];
                s[nt][0] = s[nt][1] = s[nt][2] = s[nt][3] = 0.f;
                mma16816(s[nt], qa0, qa1, qa2, qa3, b0, b1);
            }
            float mlo = s[0][0], mhi = s[0][2];
#pragma unroll
            for (int nt = 0; nt < 8; nt++) {
                mlo = fmaxf(mlo, fmaxf(s[nt][0], s[nt][1]));
                mhi = fmaxf(mhi, fmaxf(s[nt][2], s[nt][3]));
            }
            mlo = fmaxf(mlo, __shfl_xor_sync(0xffffffffu, mlo, 1));
            mlo = fmaxf(mlo, __shfl_xor_sync(0xffffffffu, mlo, 2));
            mhi = fmaxf(mhi, __shfl_xor_sync(0xffffffffu, mhi, 1));
            mhi = fmaxf(mhi, __shfl_xor_sync(0xffffffffu, mhi, 2));
            float nmlo = fmaxf(mi_lo, mlo), nmhi = fmaxf(mi_hi, mhi);
            float clo = ex2_(mi_lo - nmlo), chi = ex2_(mi_hi - nmhi);
            li_lo *= clo; li_hi *= chi;
#pragma unroll
            for (int nc = 0; nc < 8; nc++) {
                o[nc][0] *= clo; o[nc][1] *= clo; o[nc][2] *= chi; o[nc][3] *= chi;
            }
            unsigned pa[8][2];
#pragma unroll
            for (int nt = 0; nt < 8; nt++) {
                float p0 = ex2_(s[nt][0] - nmlo);
                float p1 = ex2_(s[nt][1] - nmlo);
                float p2 = ex2_(s[nt][2] - nmhi);
                float p3 = ex2_(s[nt][3] - nmhi);
                li_lo += p0 + p1;
                li_hi += p2 + p3;
                pa[nt][0] = pkbf(p0, p1);
                pa[nt][1] = pkbf(p2, p3);
            }
            mi_lo = nmlo; mi_hi = nmhi;

            const unsigned* vw = (const unsigned*)Vs + sub * 32;
#pragma unroll
            for (int nc = 0; nc < 8; nc++) {
                int c = nc * 8 + g;
                const unsigned* vr = vw + c * 68 + ti;
#pragma unroll
                for (int i = 0; i < 4; i++) {
                    unsigned b0 = vr[8 * i];
                    unsigned b1 = vr[8 * i + 4];
                    mma16816(o[nc], pa[2 * i][0], pa[2 * i][1],
                             pa[2 * i + 1][0], pa[2 * i + 1][1], b0, b1);
                }
            }
        }
    }
    li_lo += __shfl_xor_sync(0xffffffffu, li_lo, 1);
    li_lo += __shfl_xor_sync(0xffffffffu, li_lo, 2);
    li_hi += __shfl_xor_sync(0xffffffffu, li_hi, 1);
    li_hi += __shfl_xor_sync(0xffffffffu, li_hi, 2);
    float inv_lo = 1.f / li_lo, inv_hi = 1.f / li_hi;
    int q = q0 + w * 16 + g;
#pragma unroll
    for (int nc = 0; nc < 8; nc++) {
        int c = nc * 8 + ti * 2;
        sc[((long)(b * 64 + c)) * Nv + q] = o[nc][0] * inv_lo;
        sc[((long)(b * 64 + c + 1)) * Nv + q] = o[nc][1] * inv_lo;
        sc[((long)(b * 64 + c)) * Nv + q + 8] = o[nc][2] * inv_hi;
        sc[((long)(b * 64 + c + 1)) * Nv + q + 8] = o[nc][3] * inv_hi;
    }
}

// ---------------- feat_sum (f1 from raw t0 via BN1 affine-relu) + BN2 partial stats ----
__global__ void fsum_kernel(const float* __restrict__ sa, const float* __restrict__ sc,
                            const float* __restrict__ f1raw,
                            const float* __restrict__ sc1, const float* __restrict__ sh1,
                            const float* __restrict__ gamma1, const float* __restrict__ gamma2,
                            float* __restrict__ out,
                            float* __restrict__ ps, float* __restrict__ pss) {
    __shared__ float r1[256], r2[256];
    int bz = blockIdx.x;
    int b = bz >> 6, c = bz & 63;
    float g1 = gamma1[0], g2 = gamma2[0];
    float s1 = sc1[c], h1 = sh1[c];
    long base = (long)bz * Nv;
    const float4* sa4 = (const float4*)(sa + base);
    const float4* sc4 = (const float4*)(sc + base);
    const float4* f4 = (const float4*)(f1raw + base);
    float4* o4 = (float4*)(out + base);
    float s = 0.f, ss = 0.f;
    for (int i = threadIdx.x; i < 1600; i += 256) {
        float4 a = sa4[i], bb = sc4[i], f = f4[i];
        float4 v;
        v.x = g1 * a.x + g2 * bb.x + fmaxf(f.x * s1 + h1, 0.f);
        v.y = g1 * a.y + g2 * bb.y + fmaxf(f.y * s1 + h1, 0.f);
        v.z = g1 * a.z + g2 * bb.z + fmaxf(f.z * s1 + h1, 0.f);
        v.w = g1 * a.w + g2 * bb.w + fmaxf(f.w * s1 + h1, 0.f);
        o4[i] = v;
        s += v.x + v.y + v.z + v.w;
        ss += v.x * v.x + v.y * v.y + v.z * v.z + v.w * v.w;
    }
    int t = threadIdx.x;
    r1[t] = s; r2[t] = ss;
    __syncthreads();
    for (int st = 128; st > 0; st >>= 1) {
        if (t < st) { r1[t] += r1[t + st]; r2[t] += r2[t + st]; }
        __syncthreads();
    }
    if (t == 0) { ps[c * 64 + b] = r1[0]; pss[c * 64 + b] = r2[0]; }
}

// ---------------- host launch ----------------
extern "C" void kernel_launch(void* const* d_in, const int* in_sizes, int n_in,
                              void* d_out, int out_size) {
    const float* x     = (const float*)d_in[0];
    const float* Wc    = (const float*)d_in[1];
    const float* bn1g  = (const float*)d_in[2];
    const float* bn1b  = (const float*)d_in[3];
    const float* cqw   = (const float*)d_in[4];
    const float* cqb   = (const float*)d_in[5];
    const float* ckw   = (const float*)d_in[6];
    const float* ckb   = (const float*)d_in[7];
    const float* cvw   = (const float*)d_in[8];
    const float* cvb   = (const float*)d_in[9];
    const float* pqw   = (const float*)d_in[10];
    const float* pqb   = (const float*)d_in[11];
    const float* pkw   = (const float*)d_in[12];
    const float* pkb   = (const float*)d_in[13];
    const float* pvw   = (const float*)d_in[14];
    const float* pvb   = (const float*)d_in[15];
    const float* gamma1= (const float*)d_in[16];
    const float* gamma2= (const float*)d_in[17];
    const float* bn2g  = (const float*)d_in[18];
    const float* bn2b  = (const float*)d_in[19];
    const float* Wd    = (const float*)d_in[20];
    const float* bn3g  = (const float*)d_in[21];
    const float* bn3b  = (const float*)d_in[22];

    float* base = nullptr;
    cudaGetSymbolAddress((void**)&base, g_buf);
    float* t0    = base + OFF_T0;
    float* t0T   = base + OFF_T0T;
    float* t1    = base + OFF_T1;
    float* vbT   = base + OFF_VBT;
    float* sab   = base + OFF_SAB;
    float* scb   = base + OFF_SCB;
    float* qb    = base + OFF_QB;
    float* kb    = base + OFF_KB;
    float* attn  = base + OFF_ATTN;
    float* ps    = base + OFF_PS;
    float* pss   = base + OFF_PSS;
    float* sc1   = base + OFF_SC1;
    float* sh1   = base + OFF_SH1;
    __nv_bfloat16* qg = (__nv_bfloat16*)(base + OFF_QG);
    __nv_bfloat16* kg = (__nv_bfloat16*)(base + OFF_KG);
    __nv_bfloat16* vg = (__nv_bfloat16*)(base + OFF_VG);

    const int C3SMEM = 32 * 324 * 4 + 64 * 9 * 8 * 8;  // 78336
    cudaFuncSetAttribute(conv3x3_kernel<0, 1>, cudaFuncAttributeMaxDynamicSharedMemorySize,
                         C3SMEM);
    cudaFuncSetAttribute(conv3x3_kernel<1, 0>, cudaFuncAttributeMaxDynamicSharedMemorySize,
                         C3SMEM);

    dim3 cgrid(5, 5, Bv * 4), cblk(16, 8);

    // stage 1: conv_c (+T output, +fused BN1 stats) -> finalize -> apply on T
    conv3x3_kernel<0, 1><<<cgrid, cblk, C3SMEM>>>(x, Wc, nullptr, nullptr, nullptr, nullptr,
                                                  t0, t0T, ps, pss);
    bn_finalize<<<1, 64>>>(ps, pss, bn1g, bn1b, sc1, sh1, 50);
    bn_applyT_kernel<<<800, 256>>>((float4*)t0T, (const float4*)sc1, (const float4*)sh1);

    // projections (all read feat1T = t0T coalesced)
    convqk_kernel<<<dim3(13, 8, Bv), 128>>>(t0T, cqw, cqb, ckw, ckb, qb, kb);
    convqk1x1_kernel<<<dim3(Bv, 50, 2), 128>>>(t0T, pqw, pqb, pkw, pkb, qg, kg);
    conv1x1T_kernel<1, 0, 1><<<dim3(Bv, 50, 4), 128>>>(t0T, cvw, cvb, vbT);
    conv1x1T_kernel<2, 0, 1><<<dim3(Bv, 50, 4), 128>>>(t0T, pvw, pvb, vg);

    // CAM
    cam_kernel<<<Bv * Cv, 256>>>(qb, kb, attn);
    conv1x1T_kernel<0, 1, 0><<<dim3(Bv, 50, 4), 128>>>(vbT, attn, nullptr, sab);

    // PAM (flash attention via tensor cores)
    pam_mma_kernel<<<dim3(100, Bv), 128>>>(qg, kg, vg, scb);

    // combine (in-place on t0) -> conv_d (BN2 affine computed in-kernel, +BN3 stats)
    // -> final bn_apply (BN3 finalize in-kernel)
    fsum_kernel<<<Bv * Cv, 256>>>(sab, scb, t0, sc1, sh1, gamma1, gamma2, t0, ps, pss);
    conv3x3_kernel<1, 0><<<cgrid, cblk, C3SMEM>>>(t0, Wd, ps, pss, bn2g, bn2b,
                                                  t1, nullptr, ps, pss);
    bn_apply_kernel<<<800, 256>>>((const float4*)t1, (float4*)d_out, ps, pss, bn3g, bn3b);
}

// round 13
// speedup vs baseline: 1.0760x; 1.0760x over previous
#include <cuda_runtime.h>
#include <cuda_bf16.h>
#include <math.h>

#define Bv 2
#define Cv 64
#define Hv 80
#define Wv 80
#define Nv 6400
#define NQ 1600
#define NHWf 12800.0f
#define EPSV 1e-5f
#define L2E 1.44269504088896f

typedef unsigned long long ull;

// ---------------- packed helpers ----------------
__device__ __forceinline__ ull pk2(float lo, float hi) {
    ull r; asm("mov.b64 %0,{%1,%2};" : "=l"(r) : "f"(lo), "f"(hi)); return r;
}
__device__ __forceinline__ void upk2(ull v, float& lo, float& hi) {
    asm("mov.b64 {%0,%1},%2;" : "=f"(lo), "=f"(hi) : "l"(v));
}
__device__ __forceinline__ ull fma2_(ull a, ull b, ull c) {
    ull d; asm("fma.rn.f32x2 %0,%1,%2,%3;" : "=l"(d) : "l"(a), "l"(b), "l"(c)); return d;
}
__device__ __forceinline__ float ex2_(float x) {
    float y; asm("ex2.approx.ftz.f32 %0,%1;" : "=f"(y) : "f"(x)); return y;
}
__device__ __forceinline__ unsigned pkbf(float lo, float hi) {
    unsigned d; asm("cvt.rn.bf16x2.f32 %0,%1,%2;" : "=r"(d) : "f"(hi), "f"(lo)); return d;
}
__device__ __forceinline__ void mma16816(float* c, unsigned a0, unsigned a1, unsigned a2,
                                         unsigned a3, unsigned b0, unsigned b1) {
    asm("mma.sync.aligned.m16n8k16.row.col.f32.bf16.bf16.f32 "
        "{%0,%1,%2,%3},{%4,%5,%6,%7},{%8,%9},{%0,%1,%2,%3};"
        : "+f"(c[0]), "+f"(c[1]), "+f"(c[2]), "+f"(c[3])
        : "r"(a0), "r"(a1), "r"(a2), "r"(a3), "r"(b0), "r"(b1));
}
__device__ __forceinline__ void affrelu4(float* v, float4 s, float4 h) {
    v[0] = fmaxf(v[0] * s.x + h.x, 0.f);
    v[1] = fmaxf(v[1] * s.y + h.y, 0.f);
    v[2] = fmaxf(v[2] * s.z + h.z, 0.f);
    v[3] = fmaxf(v[3] * s.w + h.w, 0.f);
}

// ---------------- scratch ----------------
#define OFF_T0     0
#define OFF_T0T    (OFF_T0   + Bv*Cv*Nv)   /* [b][n][c] transposed (raw, pre-BN) */
#define OFF_T1     (OFF_T0T  + Bv*Cv*Nv)
#define OFF_VBT    (OFF_T1   + Bv*Cv*Nv)   /* [b][n][c] */
#define OFF_SAB    (OFF_VBT  + Bv*Cv*Nv)
#define OFF_SCB    (OFF_SAB  + Bv*Cv*Nv)
#define OFF_QB     (OFF_SCB  + Bv*Cv*Nv)
#define OFF_KB     (OFF_QB   + Bv*Cv*NQ)
#define OFF_ATTN   (OFF_KB   + Bv*Cv*NQ)
#define OFF_PS     (OFF_ATTN + Bv*Cv*Cv)
#define OFF_PSS    (OFF_PS   + 64*64)
#define OFF_PS2    (OFF_PSS  + 64*64)
#define OFF_PSS2   (OFF_PS2  + 128)
#define OFF_SC1    (OFF_PSS2 + 128)
#define OFF_SH1    (OFF_SC1  + 64)
#define OFF_QG     (OFF_SH1  + 64)          /* bf16 [B][N][16] */
#define OFF_KG     (OFF_QG   + Bv*Nv*8)
#define OFF_VG     (OFF_KG   + Bv*Nv*8)     /* bf16 [B][C][N] */
#define BUF_TOTAL  (OFF_VG   + Bv*Cv*Nv/2)

__device__ __align__(16) float g_buf[BUF_TOTAL];

// ---------------- conv3x3 (pad=1, no bias) + fused per-block BN stats ------------------
// grid (5,5, B*4), block (16,8) — each thread computes 2 pixels x 16 co.
// AFFINE: input BN affine computed in-kernel from psIn/pssIn (2 slots, stride 2) + g/bb.
template <int AFFINE, int WRITET>
__global__ void conv3x3_kernel(const float* __restrict__ in, const float* __restrict__ w,
                               const float* __restrict__ psIn, const float* __restrict__ pssIn,
                               const float* __restrict__ bng, const float* __restrict__ bnb,
                               float* __restrict__ out, float* __restrict__ outT,
                               float* __restrict__ ps, float* __restrict__ pss) {
    extern __shared__ float sm[];
    float* tile = sm;                                   // 32*324
    ull* w2 = (ull*)(sm + 32 * 324);                    // [ci*9+tap][8] co-pairs (all 64 ci)
    __shared__ float aff[128];
    __shared__ float red[4][32];
    int bz = blockIdx.z;
    int b = bz >> 2, co0 = (bz & 3) * 16;
    int t = threadIdx.y * 16 + threadIdx.x;             // 0..127

    float* wflat = (float*)w2;
    for (int i = t; i < 9216; i += 128) {
        int co = i & 15, r = i >> 4;
        wflat[r * 16 + co] = w[(co0 + co) * 576 + r];
    }
    if (AFFINE && t < 64) {
        float s = psIn[t * 2] + psIn[t * 2 + 1];
        float ss = pssIn[t * 2] + pssIn[t * 2 + 1];
        float m = s / NHWf;
        float var = ss / NHWf - m * m;
        float rs = rsqrtf(var + EPSV);
        float sc = bng[t] * rs;
        aff[t] = sc;
        aff[64 + t] = bnb[t] - m * sc;
    }

    int oy0 = blockIdx.y * 16, ox0 = blockIdx.x * 16;
    const float* inb = in + (long)b * Cv * Nv;

    ull acc0[8], acc1[8];
#pragma unroll
    for (int c2 = 0; c2 < 8; c2++) { acc0[c2] = pk2(0.f, 0.f); acc1[c2] = pk2(0.f, 0.f); }

    for (int chunk = 0; chunk < 2; chunk++) {
        int cbase = chunk * 32;
        __syncthreads();
        for (int i = t; i < 32 * 324; i += 128) {
            int ci = i / 324;
            int pos = i - ci * 324;
            int r = pos / 18, c2 = pos - r * 18;
            int gy = oy0 + r - 1, gx = ox0 + c2 - 1;
            float v = 0.f;
            if (gy >= 0 && gy < Hv && gx >= 0 && gx < Wv) {
                v = inb[(cbase + ci) * Nv + gy * Wv + gx];
                if (AFFINE) v = v * aff[cbase + ci] + aff[64 + cbase + ci];
            }
            tile[i] = v;
        }
        __syncthreads();

        for (int ci = 0; ci < 32; ci++) {
            const float* tp0 = tile + ci * 324 + threadIdx.y * 18 + threadIdx.x;
            const float* tp1 = tp0 + 8 * 18;
            float x0[9], x1[9];
#pragma unroll
            for (int ky = 0; ky < 3; ky++)
#pragma unroll
                for (int kx = 0; kx < 3; kx++) {
                    x0[ky * 3 + kx] = tp0[ky * 18 + kx];
                    x1[ky * 3 + kx] = tp1[ky * 18 + kx];
                }
            const ull* wr = w2 + (long)(cbase + ci) * 72;
#pragma unroll
            for (int tap = 0; tap < 9; tap++) {
                ull xd0 = pk2(x0[tap], x0[tap]);
                ull xd1 = pk2(x1[tap], x1[tap]);
#pragma unroll
                for (int c2 = 0; c2 < 8; c2++) {
                    ull wv = wr[tap * 8 + c2];
                    acc0[c2] = fma2_(xd0, wv, acc0[c2]);
                    acc1[c2] = fma2_(xd1, wv, acc1[c2]);
                }
            }
        }
    }
    int pix0 = (oy0 + threadIdx.y) * Wv + ox0 + threadIdx.x;
    int pix1 = pix0 + 8 * Wv;
    long ob0 = ((long)b * 64 + co0) * Nv + pix0;
    long ob1 = ((long)b * 64 + co0) * Nv + pix1;
    float v[16], q[16], va[16], vb2[16];
#pragma unroll
    for (int c2 = 0; c2 < 8; c2++) {
        float lo0, hi0, lo1, hi1;
        upk2(acc0[c2], lo0, hi0);
        upk2(acc1[c2], lo1, hi1);
        out[ob0 + (long)(2 * c2) * Nv] = lo0;
        out[ob0 + (long)(2 * c2 + 1) * Nv] = hi0;
        out[ob1 + (long)(2 * c2) * Nv] = lo1;
        out[ob1 + (long)(2 * c2 + 1) * Nv] = hi1;
        va[2 * c2] = lo0; va[2 * c2 + 1] = hi0;
        vb2[2 * c2] = lo1; vb2[2 * c2 + 1] = hi1;
        v[2 * c2] = lo0 + lo1; v[2 * c2 + 1] = hi0 + hi1;
        q[2 * c2] = lo0 * lo0 + lo1 * lo1; q[2 * c2 + 1] = hi0 * hi0 + hi1 * hi1;
    }
    if (WRITET) {
        float4* t0p = (float4*)(outT + ((long)b * Nv + pix0) * 64 + co0);
        float4* t1p = (float4*)(outT + ((long)b * Nv + pix1) * 64 + co0);
#pragma unroll
        for (int c4 = 0; c4 < 4; c4++) {
            t0p[c4] = make_float4(va[4 * c4], va[4 * c4 + 1], va[4 * c4 + 2], va[4 * c4 + 3]);
            t1p[c4] = make_float4(vb2[4 * c4], vb2[4 * c4 + 1], vb2[4 * c4 + 2], vb2[4 * c4 + 3]);
        }
    }
#pragma unroll
    for (int c = 0; c < 16; c++) {
#pragma unroll
        for (int off = 16; off > 0; off >>= 1) {
            v[c] += __shfl_xor_sync(0xffffffffu, v[c], off);
            q[c] += __shfl_xor_sync(0xffffffffu, q[c], off);
        }
    }
    int warp = t >> 5, lane = t & 31;
    if (lane < 16) red[warp][lane] = v[lane];
    else red[warp][lane] = q[lane - 16];
    __syncthreads();
    if (t < 32) {
        float s = 0.f;
#pragma unroll
        for (int wi = 0; wi < 4; wi++) s += red[wi][t];
        int slot = b * 25 + blockIdx.y * 5 + blockIdx.x;
        if (t < 16) ps[(co0 + t) * 64 + slot] = s;
        else pss[(co0 + t - 16) * 64 + slot] = s;
    }
}

// ---------------- BN finalize (50 slots, stride 64) ----------------
__global__ void bn_finalize(const float* __restrict__ ps, const float* __restrict__ pss,
                            const float* __restrict__ g, const float* __restrict__ bb,
                            float* __restrict__ scale, float* __restrict__ shift) {
    int c = threadIdx.x;
    float s = 0.f, ss = 0.f;
#pragma unroll 5
    for (int i = 0; i < 50; i++) { s += ps[c * 64 + i]; ss += pss[c * 64 + i]; }
    float m = s / NHWf;
    float var = ss / NHWf - m * m;
    float rs = rsqrtf(var + EPSV);
    float sc = g[c] * rs;
    scale[c] = sc;
    shift[c] = bb[c] - m * sc;
}

// ---------------- final BN apply (+relu), [c][n] ----------------
__global__ void bn_apply_kernel(const float4* __restrict__ in, float4* __restrict__ out,
                                const float* __restrict__ scale, const float* __restrict__ shift) {
    int i = blockIdx.x * 256 + threadIdx.x;
    int c = (i / 1600) & 63;
    float sc = scale[c], sh = shift[c];
    float4 v = in[i];
    v.x = fmaxf(v.x * sc + sh, 0.f);
    v.y = fmaxf(v.y * sc + sh, 0.f);
    v.z = fmaxf(v.z * sc + sh, 0.f);
    v.w = fmaxf(v.w * sc + sh, 0.f);
    out[i] = v;
}

// ---------------- MEGA projection kernel: all 4 projection families in one launch -------
// grid 1208 x 128 threads. Reads RAW t0T [n][c]; applies BN1 affine+relu inline.
//  blocks [0,208):    convqk  (q+k conv2x2/s2, 8 co each)   decode: b, cogrp(8), pxchunk(13)
//  blocks [208,408):  pq/pk 1x1 -> bf16 [n][16]
//  blocks [408,1208): cv (->vbT f32 [n][c]) and pv (->vg bf16 [c][n]), 16-co groups
__global__ void __launch_bounds__(128) proj_kernel(
    const float* __restrict__ t0T,
    const float* __restrict__ sc1, const float* __restrict__ sh1,
    const float* __restrict__ cqw, const float* __restrict__ cqb,
    const float* __restrict__ ckw, const float* __restrict__ ckb,
    const float* __restrict__ pqw, const float* __restrict__ pqb,
    const float* __restrict__ pkw, const float* __restrict__ pkb,
    const float* __restrict__ cvw, const float* __restrict__ cvb,
    const float* __restrict__ pvw, const float* __restrict__ pvb,
    float* __restrict__ qb, float* __restrict__ kb,
    __nv_bfloat16* __restrict__ qg, __nv_bfloat16* __restrict__ kg,
    float* __restrict__ vbT, __nv_bfloat16* __restrict__ vg) {
    __shared__ __align__(16) float smem[4224];
    float* aff = smem + 4096;
    int t = threadIdx.x;
    aff[t] = (t < 64) ? sc1[t] : sh1[t - 64];
    const float4* asc4 = (const float4*)aff;
    const float4* ash4 = (const float4*)(aff + 64);
    int a = blockIdx.x;

    if (a < 208) {
        // ---- convqk: q AND k, 8 co each, input read once ----
        int b = a / 104, r = a % 104;
        int co0 = (r / 13) * 8, px = r % 13;
        float* wsmq = smem;
        float* wsmk = smem + 2048;
        for (int i = t; i < 2048; i += 128) {
            int co = i & 7, rr = i >> 3;
            wsmq[rr * 8 + co] = cqw[(co0 + co) * 256 + rr];
            wsmk[rr * 8 + co] = ckw[(co0 + co) * 256 + rr];
        }
        __syncthreads();
        int p = px * 128 + t;
        if (p >= NQ) return;
        int oy = p / 40, ox = p % 40;
        const float* f1b = t0T + (long)b * Nv * 64;
        const float4* p00 = (const float4*)(f1b + ((2 * oy) * Wv + 2 * ox) * 64);
        const float4* p01 = p00 + 16;
        const float4* p10 = (const float4*)(f1b + ((2 * oy + 1) * Wv + 2 * ox) * 64);
        const float4* p11 = p10 + 16;
        ull aq[4], ak[4];
        const ull* w2q = (const ull*)wsmq;
        const ull* w2k = (const ull*)wsmk;
#pragma unroll
        for (int c2 = 0; c2 < 4; c2++) {
            aq[c2] = pk2(cqb[co0 + 2 * c2], cqb[co0 + 2 * c2 + 1]);
            ak[c2] = pk2(ckb[co0 + 2 * c2], ckb[co0 + 2 * c2 + 1]);
        }
#pragma unroll 4
        for (int ci4 = 0; ci4 < 16; ci4++) {
            float4 s4 = asc4[ci4], h4 = ash4[ci4];
            float a0[4], a1[4], a2[4], a3[4];
            *(float4*)a0 = p00[ci4];
            *(float4*)a1 = p01[ci4];
            *(float4*)a2 = p10[ci4];
            *(float4*)a3 = p11[ci4];
            affrelu4(a0, s4, h4);
            affrelu4(a1, s4, h4);
            affrelu4(a2, s4, h4);
            affrelu4(a3, s4, h4);
#pragma unroll
            for (int j = 0; j < 4; j++) {
                ull x0 = pk2(a0[j], a0[j]), x1 = pk2(a1[j], a1[j]);
                ull x2 = pk2(a2[j], a2[j]), x3 = pk2(a3[j], a3[j]);
                int ci = ci4 * 4 + j;
                const ull* wrq = w2q + ci * 16;
                const ull* wrk = w2k + ci * 16;
#pragma unroll
                for (int c2 = 0; c2 < 4; c2++) {
                    ull e = fma2_(x0, wrq[c2], aq[c2]);
                    e = fma2_(x1, wrq[4 + c2], e);
                    e = fma2_(x2, wrq[8 + c2], e);
                    aq[c2] = fma2_(x3, wrq[12 + c2], e);
                    ull f = fma2_(x0, wrk[c2], ak[c2]);
                    f = fma2_(x1, wrk[4 + c2], f);
                    f = fma2_(x2, wrk[8 + c2], f);
                    ak[c2] = fma2_(x3, wrk[12 + c2], f);
                }
            }
        }
        long obase = ((long)b * 64 + co0) * NQ + p;
#pragma unroll
        for (int c2 = 0; c2 < 4; c2++) {
            float lo, hi;
            upk2(aq[c2], lo, hi);
            qb[obase + (long)(2 * c2) * NQ] = lo;
            qb[obase + (long)(2 * c2 + 1) * NQ] = hi;
            upk2(ak[c2], lo, hi);
            kb[obase + (long)(2 * c2) * NQ] = lo;
            kb[obase + (long)(2 * c2 + 1) * NQ] = hi;
        }
    } else if (a < 408) {
        // ---- pq/pk 1x1 conv (8 outs) -> bf16 [n][16] ----
        int id = a - 208;
        int which = id / 100, r2 = id % 100;
        int b = r2 / 50, ny = r2 % 50;
        const float* w = which ? pkw : pqw;
        const float* bias = which ? pkb : pqb;
        __nv_bfloat16* outg = which ? kg : qg;
        float osc = which ? 1.f : L2E;
        float* wsm = smem;
        for (int i = t; i < 512; i += 128) {
            int co = i >> 6, ci = i & 63;
            wsm[ci * 8 + co] = w[i];
        }
        __syncthreads();
        int n = ny * 128 + t;
        float acc[8];
#pragma unroll
        for (int j = 0; j < 8; j++) acc[j] = bias[j];
        const float4* inp = (const float4*)(t0T + ((long)b * Nv + n) * 64);
        const float4* w4p = (const float4*)wsm;
#pragma unroll 4
        for (int ci4 = 0; ci4 < 16; ci4++) {
            float va[4];
            *(float4*)va = inp[ci4];
            affrelu4(va, asc4[ci4], ash4[ci4]);
#pragma unroll
            for (int j = 0; j < 4; j++) {
                float xv = va[j];
                int ci = ci4 * 4 + j;
#pragma unroll
                for (int c4 = 0; c4 < 2; c4++) {
                    float4 w4 = w4p[ci * 2 + c4];
                    acc[c4 * 4 + 0] += w4.x * xv; acc[c4 * 4 + 1] += w4.y * xv;
                    acc[c4 * 4 + 2] += w4.z * xv; acc[c4 * 4 + 3] += w4.w * xv;
                }
            }
        }
        uint4* qd = (uint4*)(outg + ((long)b * Nv + n) * 16);
        qd[0] = make_uint4(pkbf(acc[0] * osc, acc[1] * osc), pkbf(acc[2] * osc, acc[3] * osc),
                           pkbf(acc[4] * osc, acc[5] * osc), pkbf(acc[6] * osc, acc[7] * osc));
        qd[1] = make_uint4(0u, 0u, 0u, 0u);
    } else {
        // ---- cv (-> vbT f32 [n][c]) / pv (-> vg bf16 [c][n]), 16-co groups ----
        int id = a - 408;
        int which = id / 400;
        id -= which * 400;
        int z = id / 100, r2 = id % 100;
        int b = r2 / 50, ny = r2 % 50;
        int co0 = z * 16;
        const float* w = which ? pvw : cvw;
        const float* bias = which ? pvb : cvb;
        float* wsm = smem;
        for (int i = t; i < 1024; i += 128) {
            int co = i >> 6, ci = i & 63;
            wsm[ci * 16 + co] = w[(co0 + co) * 64 + ci];
        }
        __syncthreads();
        int n = ny * 128 + t;
        float acc[16];
#pragma unroll
        for (int co = 0; co < 16; co++) acc[co] = bias[co0 + co];
        const float4* inp = (const float4*)(t0T + ((long)b * Nv + n) * 64);
        const float4* wsm4 = (const float4*)wsm;
#pragma unroll 4
        for (int ci4 = 0; ci4 < 16; ci4++) {
            float va[4];
            *(float4*)va = inp[ci4];
            affrelu4(va, asc4[ci4], ash4[ci4]);
#pragma unroll
            for (int j = 0; j < 4; j++) {
                float xv = va[j];
#pragma unroll
                for (int c4 = 0; c4 < 4; c4++) {
                    float4 w4 = wsm4[(ci4 * 4 + j) * 4 + c4];
                    acc[c4 * 4 + 0] += w4.x * xv;
                    acc[c4 * 4 + 1] += w4.y * xv;
                    acc[c4 * 4 + 2] += w4.z * xv;
                    acc[c4 * 4 + 3] += w4.w * xv;
                }
            }
        }
        if (which == 0) {
            float4* ob = (float4*)(vbT + ((long)b * Nv + n) * 64 + co0);
#pragma unroll
            for (int c4 = 0; c4 < 4; c4++)
                ob[c4] = make_float4(acc[4 * c4], acc[4 * c4 + 1], acc[4 * c4 + 2],
                                     acc[4 * c4 + 3]);
        } else {
            __nv_bfloat16* ob = vg + ((long)b * 64 + co0) * Nv + n;
#pragma unroll
            for (int co = 0; co < 16; co++) ob[(long)co * Nv] = __float2bfloat16(acc[co]);
        }
    }
}

// ---------------- conv1x1 from [n][c] input, 16-co groups (sab only) -------------------
__global__ void conv1x1T_kernel(const float* __restrict__ inT, const float* __restrict__ w,
                                float* __restrict__ out) {
    __shared__ __align__(16) float wsm[1024];
    int b = blockIdx.x;
    int co0 = blockIdx.z * 16;
    int n = blockIdx.y * 128 + threadIdx.x;
    const float* wb = w + (long)b * 4096;
    for (int i = threadIdx.x; i < 1024; i += 128) {
        int co = i >> 6, ci = i & 63;
        wsm[ci * 16 + co] = wb[(co0 + co) * 64 + ci];
    }
    __syncthreads();
    float acc[16];
#pragma unroll
    for (int co = 0; co < 16; co++) acc[co] = 0.f;
    const float4* inp = (const float4*)(inT + ((long)b * Nv + n) * 64);
    const float4* wsm4 = (const float4*)wsm;
#pragma unroll 4
    for (int ci4 = 0; ci4 < 16; ci4++) {
        float va[4];
        *(float4*)va = inp[ci4];
#pragma unroll
        for (int j = 0; j < 4; j++) {
            float xv = va[j];
#pragma unroll
            for (int c4 = 0; c4 < 4; c4++) {
                float4 w4 = wsm4[(ci4 * 4 + j) * 4 + c4];
                acc[c4 * 4 + 0] += w4.x * xv;
                acc[c4 * 4 + 1] += w4.y * xv;
                acc[c4 * 4 + 2] += w4.z * xv;
                acc[c4 * 4 + 3] += w4.w * xv;
            }
        }
    }
    float* ob = out + ((long)b * 64 + co0) * Nv + n;
#pragma unroll
    for (int co = 0; co < 16; co++) ob[(long)co * Nv] = acc[co];
}

// ---------------- CAM energy + softmax, 256 threads ----------------
__global__ void cam_kernel(const float* __restrict__ q, const float* __restrict__ k,
                           float* __restrict__ attn) {
    __shared__ __align__(16) float qsm[NQ];
    __shared__ float part[256];
    __shared__ float er[64];
    __shared__ float pe[64];
    int b = blockIdx.x >> 6, c = blockIdx.x & 63;
    const float* qr = q + (long)(b * 64 + c) * NQ;
    for (int i = threadIdx.x; i < 400; i += 256)
        ((float4*)qsm)[i] = ((const float4*)qr)[i];
    __syncthreads();
    int d = threadIdx.x & 63;
    int slice = threadIdx.x >> 6;
    const float4* kr = (const float4*)(k + (long)(b * 64 + d) * NQ) + slice * 100;
    const float4* q4 = (const float4*)qsm + slice * 100;
    float s = 0.f;
#pragma unroll 4
    for (int i = 0; i < 100; i++) {
        float4 kv = kr[i];
        float4 qv = q4[i];
        s += qv.x * kv.x + qv.y * kv.y + qv.z * kv.z + qv.w * kv.w;
    }
    part[slice * 64 + d] = s;
    __syncthreads();
    if (threadIdx.x < 64) {
        int dd = threadIdx.x;
        er[dd] = part[dd] + part[64 + dd] + part[128 + dd] + part[192 + dd];
    }
    __syncthreads();
    if (threadIdx.x < 64) {
        int dd = threadIdx.x;
        float e = er[dd];
        float mn = er[0];
        for (int i = 1; i < 64; i++) mn = fminf(mn, er[i]);
        pe[dd] = __expf(mn - e);
    }
    __syncthreads();
    if (threadIdx.x < 64) {
        int dd = threadIdx.x;
        float sum = 0.f;
        for (int i = 0; i < 64; i++) sum += pe[i];
        attn[(long)(b * 64 + c) * 64 + dd] = pe[dd] / sum;
    }
}

// ---------------- PAM: flash attention via mma.sync bf16, 128-key tiles ----------------
__global__ void __launch_bounds__(128) pam_mma_kernel(
    const __nv_bfloat16* __restrict__ qg, const __nv_bfloat16* __restrict__ kg,
    const __nv_bfloat16* __restrict__ vg, float* __restrict__ sc) {
    __shared__ __align__(16) __nv_bfloat16 Qs[64 * 16];
    __shared__ __align__(16) __nv_bfloat16 Ks[128 * 16];
    __shared__ __align__(16) __nv_bfloat16 Vs[64 * 136];
    int b = blockIdx.y;
    int q0 = blockIdx.x * 64;
    int t = threadIdx.x, w = t >> 5, lane = t & 31;
    int g = lane >> 2, ti = lane & 3;

    ((uint4*)Qs)[t] = ((const uint4*)(qg + ((long)b * Nv + q0) * 16))[t];
    __syncthreads();

    unsigned qa0, qa1, qa2, qa3;
    {
        const unsigned* qw = (const unsigned*)Qs;
        int r = w * 16 + g;
        qa0 = qw[r * 8 + ti];
        qa1 = qw[(r + 8) * 8 + ti];
        qa2 = qw[r * 8 + ti + 4];
        qa3 = qw[(r + 8) * 8 + ti + 4];
    }

    float o[8][4];
#pragma unroll
    for (int nc = 0; nc < 8; nc++) { o[nc][0] = o[nc][1] = o[nc][2] = o[nc][3] = 0.f; }
    float li_lo = 0.f, li_hi = 0.f, mi_lo = -1e30f, mi_hi = -1e30f;

    for (int j0 = 0; j0 < Nv; j0 += 128) {
        __syncthreads();
        {
            const uint4* src = (const uint4*)(kg + ((long)b * Nv + j0) * 16);
            ((uint4*)Ks)[t] = src[t];
            ((uint4*)Ks)[t + 128] = src[t + 128];
        }
#pragma unroll
        for (int i = t; i < 1024; i += 128) {
            int c = i >> 4, h = i & 15;
            *(uint4*)(Vs + c * 136 + h * 8) =
                *(const uint4*)(vg + ((long)(b * 64 + c)) * Nv + j0 + h * 8);
        }
        __syncthreads();

#pragma unroll
        for (int sub = 0; sub < 2; sub++) {
            float s[8][4];
            const unsigned* kw = (const unsigned*)Ks + sub * 512;
#pragma unroll
            for (int nt = 0; nt < 8; nt++) {
                int j = nt * 8 + g;
                unsigned b0 = kw[j * 8 + ti];
                unsigned b1 = kw[j * 8 + ti + 4];
                s[nt][0] = s[nt][1] = s[nt][2] = s[nt][3] = 0.f;
                mma16816(s[nt], qa0, qa1, qa2, qa3, b0, b1);
            }
            float mlo = s[0][0], mhi = s[0][2];
#pragma unroll
            for (int nt = 0; nt < 8; nt++) {
                mlo = fmaxf(mlo, fmaxf(s[nt][0], s[nt][1]));
                mhi = fmaxf(mhi, fmaxf(s[nt][2], s[nt][3]));
            }
            mlo = fmaxf(mlo, __shfl_xor_sync(0xffffffffu, mlo, 1));
            mlo = fmaxf(mlo, __shfl_xor_sync(0xffffffffu, mlo, 2));
            mhi = fmaxf(mhi, __shfl_xor_sync(0xffffffffu, mhi, 1));
            mhi = fmaxf(mhi, __shfl_xor_sync(0xffffffffu, mhi, 2));
            float nmlo = fmaxf(mi_lo, mlo), nmhi = fmaxf(mi_hi, mhi);
            float clo = ex2_(mi_lo - nmlo), chi = ex2_(mi_hi - nmhi);
            li_lo *= clo; li_hi *= chi;
#pragma unroll
            for (int nc = 0; nc < 8; nc++) {
                o[nc][0] *= clo; o[nc][1] *= clo; o[nc][2] *= chi; o[nc][3] *= chi;
            }
            unsigned pa[8][2];
#pragma unroll
            for (int nt = 0; nt < 8; nt++) {
                float p0 = ex2_(s[nt][0] - nmlo);
                float p1 = ex2_(s[nt][1] - nmlo);
                float p2 = ex2_(s[nt][2] - nmhi);
                float p3 = ex2_(s[nt][3] - nmhi);
                li_lo += p0 + p1;
                li_hi += p2 + p3;
                pa[nt][0] = pkbf(p0, p1);
                pa[nt][1] = pkbf(p2, p3);
            }
            mi_lo = nmlo; mi_hi = nmhi;

            const unsigned* vw = (const unsigned*)Vs + sub * 32;
#pragma unroll
            for (int nc = 0; nc < 8; nc++) {
                int c = nc * 8 + g;
                const unsigned* vr = vw + c * 68 + ti;
#pragma unroll
                for (int i = 0; i < 4; i++) {
                    unsigned b0 = vr[8 * i];
                    unsigned b1 = vr[8 * i + 4];
                    mma16816(o[nc], pa[2 * i][0], pa[2 * i][1],
                             pa[2 * i + 1][0], pa[2 * i + 1][1], b0, b1);
                }
            }
        }
    }
    li_lo += __shfl_xor_sync(0xffffffffu, li_lo, 1);
    li_lo += __shfl_xor_sync(0xffffffffu, li_lo, 2);
    li_hi += __shfl_xor_sync(0xffffffffu, li_hi, 1);
    li_hi += __shfl_xor_sync(0xffffffffu, li_hi, 2);
    float inv_lo = 1.f / li_lo, inv_hi = 1.f / li_hi;
    int q = q0 + w * 16 + g;
#pragma unroll
    for (int nc = 0; nc < 8; nc++) {
        int c = nc * 8 + ti * 2;
        sc[((long)(b * 64 + c)) * Nv + q] = o[nc][0] * inv_lo;
        sc[((long)(b * 64 + c + 1)) * Nv + q] = o[nc][1] * inv_lo;
        sc[((long)(b * 64 + c)) * Nv + q + 8] = o[nc][2] * inv_hi;
        sc[((long)(b * 64 + c + 1)) * Nv + q + 8] = o[nc][3] * inv_hi;
    }
}

// ---------------- feat_sum (BN1 affine-relu on raw t0) + BN2 stats (2-slot stride) -----
__global__ void fsum_kernel(const float* __restrict__ sa, const float* __restrict__ sc,
                            const float* __restrict__ f1raw,
                            const float* __restrict__ sc1, const float* __restrict__ sh1,
                            const float* __restrict__ gamma1, const float* __restrict__ gamma2,
                            float* __restrict__ out,
                            float* __restrict__ ps2, float* __restrict__ pss2) {
    __shared__ float r1[256], r2[256];
    int bz = blockIdx.x;
    int b = bz >> 6, c = bz & 63;
    float g1 = gamma1[0], g2 = gamma2[0];
    float s1 = sc1[c], h1 = sh1[c];
    long base = (long)bz * Nv;
    const float4* sa4 = (const float4*)(sa + base);
    const float4* sc4 = (const float4*)(sc + base);
    const float4* f4 = (const float4*)(f1raw + base);
    float4* o4 = (float4*)(out + base);
    float s = 0.f, ss = 0.f;
    for (int i = threadIdx.x; i < 1600; i += 256) {
        float4 a = sa4[i], bb = sc4[i], f = f4[i];
        float4 v;
        v.x = g1 * a.x + g2 * bb.x + fmaxf(f.x * s1 + h1, 0.f);
        v.y = g1 * a.y + g2 * bb.y + fmaxf(f.y * s1 + h1, 0.f);
        v.z = g1 * a.z + g2 * bb.z + fmaxf(f.z * s1 + h1, 0.f);
        v.w = g1 * a.w + g2 * bb.w + fmaxf(f.w * s1 + h1, 0.f);
        o4[i] = v;
        s += v.x + v.y + v.z + v.w;
        ss += v.x * v.x + v.y * v.y + v.z * v.z + v.w * v.w;
    }
    int t = threadIdx.x;
    r1[t] = s; r2[t] = ss;
    __syncthreads();
    for (int st = 128; st > 0; st >>= 1) {
        if (t < st) { r1[t] += r1[t + st]; r2[t] += r2[t + st]; }
        __syncthreads();
    }
    if (t == 0) { ps2[c * 2 + b] = r1[0]; pss2[c * 2 + b] = r2[0]; }
}

// ---------------- host launch ----------------
extern "C" void kernel_launch(void* const* d_in, const int* in_sizes, int n_in,
                              void* d_out, int out_size) {
    const float* x     = (const float*)d_in[0];
    const float* Wc    = (const float*)d_in[1];
    const float* bn1g  = (const float*)d_in[2];
    const float* bn1b  = (const float*)d_in[3];
    const float* cqw   = (const float*)d_in[4];
    const float* cqb   = (const float*)d_in[5];
    const float* ckw   = (const float*)d_in[6];
    const float* ckb   = (const float*)d_in[7];
    const float* cvw   = (const float*)d_in[8];
    const float* cvb   = (const float*)d_in[9];
    const float* pqw   = (const float*)d_in[10];
    const float* pqb   = (const float*)d_in[11];
    const float* pkw   = (const float*)d_in[12];
    const float* pkb   = (const float*)d_in[13];
    const float* pvw   = (const float*)d_in[14];
    const float* pvb   = (const float*)d_in[15];
    const float* gamma1= (const float*)d_in[16];
    const float* gamma2= (const float*)d_in[17];
    const float* bn2g  = (const float*)d_in[18];
    const float* bn2b  = (const float*)d_in[19];
    const float* Wd    = (const float*)d_in[20];
    const float* bn3g  = (const float*)d_in[21];
    const float* bn3b  = (const float*)d_in[22];

    float* base = nullptr;
    cudaGetSymbolAddress((void**)&base, g_buf);
    float* t0    = base + OFF_T0;
    float* t0T   = base + OFF_T0T;
    float* t1    = base + OFF_T1;
    float* vbT   = base + OFF_VBT;
    float* sab   = base + OFF_SAB;
    float* scb   = base + OFF_SCB;
    float* qb    = base + OFF_QB;
    float* kb    = base + OFF_KB;
    float* attn  = base + OFF_ATTN;
    float* ps    = base + OFF_PS;
    float* pss   = base + OFF_PSS;
    float* ps2   = base + OFF_PS2;
    float* pss2  = base + OFF_PSS2;
    float* sc1   = base + OFF_SC1;
    float* sh1   = base + OFF_SH1;
    __nv_bfloat16* qg = (__nv_bfloat16*)(base + OFF_QG);
    __nv_bfloat16* kg = (__nv_bfloat16*)(base + OFF_KG);
    __nv_bfloat16* vg = (__nv_bfloat16*)(base + OFF_VG);

    const int C3SMEM = 32 * 324 * 4 + 64 * 9 * 8 * 8;  // 78336
    cudaFuncSetAttribute(conv3x3_kernel<0, 1>, cudaFuncAttributeMaxDynamicSharedMemorySize,
                         C3SMEM);
    cudaFuncSetAttribute(conv3x3_kernel<1, 0>, cudaFuncAttributeMaxDynamicSharedMemorySize,
                         C3SMEM);

    dim3 cgrid(5, 5, Bv * 4), cblk(16, 8);

    // 1-2: conv_c (+raw T output, +BN1 stats) -> BN1 finalize
    conv3x3_kernel<0, 1><<<cgrid, cblk, C3SMEM>>>(x, Wc, nullptr, nullptr, nullptr, nullptr,
                                                  t0, t0T, ps, pss);
    bn_finalize<<<1, 64>>>(ps, pss, bn1g, bn1b, sc1, sh1);

    // 3: all projections in one launch (BN1 affine-relu inline)
    proj_kernel<<<1208, 128>>>(t0T, sc1, sh1, cqw, cqb, ckw, ckb, pqw, pqb, pkw, pkb,
                               cvw, cvb, pvw, pvb, qb, kb, qg, kg, vbT, vg);

    // 4-5: CAM
    cam_kernel<<<Bv * Cv, 256>>>(qb, kb, attn);
    conv1x1T_kernel<<<dim3(Bv, 50, 4), 128>>>(vbT, attn, sab);

    // 6: PAM
    pam_mma_kernel<<<dim3(100, Bv), 128>>>(qg, kg, vg, scb);

    // 7-10: combine -> conv_d (BN2 affine in-kernel, +BN3 stats) -> finalize -> apply
    fsum_kernel<<<Bv * Cv, 256>>>(sab, scb, t0, sc1, sh1, gamma1, gamma2, t0, ps2, pss2);
    conv3x3_kernel<1, 0><<<cgrid, cblk, C3SMEM>>>(t0, Wd, ps2, pss2, bn2g, bn2b,
                                                  t1, nullptr, ps, pss);
    bn_finalize<<<1, 64>>>(ps, pss, bn3g, bn3b, sc1, sh1);
    bn_apply_kernel<<<800, 256>>>((const float4*)t1, (float4*)d_out, sc1, sh1);
}

// round 14
// speedup vs baseline: 1.0822x; 1.0058x over previous
#include <cuda_runtime.h>
#include <cuda_bf16.h>
#include <math.h>

#define Bv 2
#define Cv 64
#define Hv 80
#define Wv 80
#define Nv 6400
#define NQ 1600
#define NHWf 12800.0f
#define EPSV 1e-5f
#define L2E 1.44269504088896f

typedef unsigned long long ull;

// ---------------- packed helpers ----------------
__device__ __forceinline__ ull pk2(float lo, float hi) {
    ull r; asm("mov.b64 %0,{%1,%2};" : "=l"(r) : "f"(lo), "f"(hi)); return r;
}
__device__ __forceinline__ void upk2(ull v, float& lo, float& hi) {
    asm("mov.b64 {%0,%1},%2;" : "=f"(lo), "=f"(hi) : "l"(v));
}
__device__ __forceinline__ ull fma2_(ull a, ull b, ull c) {
    ull d; asm("fma.rn.f32x2 %0,%1,%2,%3;" : "=l"(d) : "l"(a), "l"(b), "l"(c)); return d;
}
__device__ __forceinline__ float ex2_(float x) {
    float y; asm("ex2.approx.ftz.f32 %0,%1;" : "=f"(y) : "f"(x)); return y;
}
__device__ __forceinline__ unsigned pkbf(float lo, float hi) {
    unsigned d; asm("cvt.rn.bf16x2.f32 %0,%1,%2;" : "=r"(d) : "f"(hi), "f"(lo)); return d;
}
__device__ __forceinline__ void mma16816(float* c, unsigned a0, unsigned a1, unsigned a2,
                                         unsigned a3, unsigned b0, unsigned b1) {
    asm("mma.sync.aligned.m16n8k16.row.col.f32.bf16.bf16.f32 "
        "{%0,%1,%2,%3},{%4,%5,%6,%7},{%8,%9},{%0,%1,%2,%3};"
        : "+f"(c[0]), "+f"(c[1]), "+f"(c[2]), "+f"(c[3])
        : "r"(a0), "r"(a1), "r"(a2), "r"(a3), "r"(b0), "r"(b1));
}
__device__ __forceinline__ void affrelu4(float* v, float4 s, float4 h) {
    v[0] = fmaxf(v[0] * s.x + h.x, 0.f);
    v[1] = fmaxf(v[1] * s.y + h.y, 0.f);
    v[2] = fmaxf(v[2] * s.z + h.z, 0.f);
    v[3] = fmaxf(v[3] * s.w + h.w, 0.f);
}

// ---------------- scratch ----------------
#define OFF_T0     0
#define OFF_T0T    (OFF_T0   + Bv*Cv*Nv)   /* [b][n][c] transposed (raw, pre-BN) */
#define OFF_T1     (OFF_T0T  + Bv*Cv*Nv)
#define OFF_VBT    (OFF_T1   + Bv*Cv*Nv)   /* [b][n][c] */
#define OFF_SAB    (OFF_VBT  + Bv*Cv*Nv)
#define OFF_SCB    (OFF_SAB  + Bv*Cv*Nv)
#define OFF_QB     (OFF_SCB  + Bv*Cv*Nv)
#define OFF_KB     (OFF_QB   + Bv*Cv*NQ)
#define OFF_ATTN   (OFF_KB   + Bv*Cv*NQ)
#define OFF_PS     (OFF_ATTN + Bv*Cv*Cv)
#define OFF_PSS    (OFF_PS   + 64*64)
#define OFF_PS2    (OFF_PSS  + 64*64)
#define OFF_PSS2   (OFF_PS2  + 128)
#define OFF_SC1    (OFF_PSS2 + 128)
#define OFF_SH1    (OFF_SC1  + 64)
#define OFF_QG     (OFF_SH1  + 64)          /* bf16 [B][N][16] */
#define OFF_KG     (OFF_QG   + Bv*Nv*8)
#define OFF_VG     (OFF_KG   + Bv*Nv*8)     /* bf16 [B][C][N] */
#define BUF_TOTAL  (OFF_VG   + Bv*Cv*Nv/2)

__device__ __align__(16) float g_buf[BUF_TOTAL];

// ---------------- conv3x3 (pad=1, no bias) + fused per-block BN stats ------------------
// grid (5,5, B*4), block (16,8) — each thread computes 2 pixels x 16 co.
// AFFINE: input BN affine computed in-kernel from psIn/pssIn (2 slots, stride 2) + g/bb.
template <int AFFINE, int WRITET>
__global__ void conv3x3_kernel(const float* __restrict__ in, const float* __restrict__ w,
                               const float* __restrict__ psIn, const float* __restrict__ pssIn,
                               const float* __restrict__ bng, const float* __restrict__ bnb,
                               float* __restrict__ out, float* __restrict__ outT,
                               float* __restrict__ ps, float* __restrict__ pss) {
    extern __shared__ float sm[];
    float* tile = sm;                                   // 32*324
    ull* w2 = (ull*)(sm + 32 * 324);                    // [ci*9+tap][8] co-pairs (all 64 ci)
    __shared__ float aff[128];
    __shared__ float red[4][32];
    int bz = blockIdx.z;
    int b = bz >> 2, co0 = (bz & 3) * 16;
    int t = threadIdx.y * 16 + threadIdx.x;             // 0..127

    float* wflat = (float*)w2;
    for (int i = t; i < 9216; i += 128) {
        int co = i & 15, r = i >> 4;
        wflat[r * 16 + co] = w[(co0 + co) * 576 + r];
    }
    if (AFFINE && t < 64) {
        float s = psIn[t * 2] + psIn[t * 2 + 1];
        float ss = pssIn[t * 2] + pssIn[t * 2 + 1];
        float m = s / NHWf;
        float var = ss / NHWf - m * m;
        float rs = rsqrtf(var + EPSV);
        float sc = bng[t] * rs;
        aff[t] = sc;
        aff[64 + t] = bnb[t] - m * sc;
    }

    int oy0 = blockIdx.y * 16, ox0 = blockIdx.x * 16;
    const float* inb = in + (long)b * Cv * Nv;

    ull acc0[8], acc1[8];
#pragma unroll
    for (int c2 = 0; c2 < 8; c2++) { acc0[c2] = pk2(0.f, 0.f); acc1[c2] = pk2(0.f, 0.f); }

    for (int chunk = 0; chunk < 2; chunk++) {
        int cbase = chunk * 32;
        __syncthreads();
        for (int i = t; i < 32 * 324; i += 128) {
            int ci = i / 324;
            int pos = i - ci * 324;
            int r = pos / 18, c2 = pos - r * 18;
            int gy = oy0 + r - 1, gx = ox0 + c2 - 1;
            float v = 0.f;
            if (gy >= 0 && gy < Hv && gx >= 0 && gx < Wv) {
                v = inb[(cbase + ci) * Nv + gy * Wv + gx];
                if (AFFINE) v = v * aff[cbase + ci] + aff[64 + cbase + ci];
            }
            tile[i] = v;
        }
        __syncthreads();

        for (int ci = 0; ci < 32; ci++) {
            const float* tp0 = tile + ci * 324 + threadIdx.y * 18 + threadIdx.x;
            const float* tp1 = tp0 + 8 * 18;
            float x0[9], x1[9];
#pragma unroll
            for (int ky = 0; ky < 3; ky++)
#pragma unroll
                for (int kx = 0; kx < 3; kx++) {
                    x0[ky * 3 + kx] = tp0[ky * 18 + kx];
                    x1[ky * 3 + kx] = tp1[ky * 18 + kx];
                }
            const ull* wr = w2 + (long)(cbase + ci) * 72;
#pragma unroll
            for (int tap = 0; tap < 9; tap++) {
                ull xd0 = pk2(x0[tap], x0[tap]);
                ull xd1 = pk2(x1[tap], x1[tap]);
#pragma unroll
                for (int c2 = 0; c2 < 8; c2++) {
                    ull wv = wr[tap * 8 + c2];
                    acc0[c2] = fma2_(xd0, wv, acc0[c2]);
                    acc1[c2] = fma2_(xd1, wv, acc1[c2]);
                }
            }
        }
    }
    int pix0 = (oy0 + threadIdx.y) * Wv + ox0 + threadIdx.x;
    int pix1 = pix0 + 8 * Wv;
    long ob0 = ((long)b * 64 + co0) * Nv + pix0;
    long ob1 = ((long)b * 64 + co0) * Nv + pix1;
    float v[16], q[16], va[16], vb2[16];
#pragma unroll
    for (int c2 = 0; c2 < 8; c2++) {
        float lo0, hi0, lo1, hi1;
        upk2(acc0[c2], lo0, hi0);
        upk2(acc1[c2], lo1, hi1);
        out[ob0 + (long)(2 * c2) * Nv] = lo0;
        out[ob0 + (long)(2 * c2 + 1) * Nv] = hi0;
        out[ob1 + (long)(2 * c2) * Nv] = lo1;
        out[ob1 + (long)(2 * c2 + 1) * Nv] = hi1;
        va[2 * c2] = lo0; va[2 * c2 + 1] = hi0;
        vb2[2 * c2] = lo1; vb2[2 * c2 + 1] = hi1;
        v[2 * c2] = lo0 + lo1; v[2 * c2 + 1] = hi0 + hi1;
        q[2 * c2] = lo0 * lo0 + lo1 * lo1; q[2 * c2 + 1] = hi0 * hi0 + hi1 * hi1;
    }
    if (WRITET) {
        float4* t0p = (float4*)(outT + ((long)b * Nv + pix0) * 64 + co0);
        float4* t1p = (float4*)(outT + ((long)b * Nv + pix1) * 64 + co0);
#pragma unroll
        for (int c4 = 0; c4 < 4; c4++) {
            t0p[c4] = make_float4(va[4 * c4], va[4 * c4 + 1], va[4 * c4 + 2], va[4 * c4 + 3]);
            t1p[c4] = make_float4(vb2[4 * c4], vb2[4 * c4 + 1], vb2[4 * c4 + 2], vb2[4 * c4 + 3]);
        }
    }
#pragma unroll
    for (int c = 0; c < 16; c++) {
#pragma unroll
        for (int off = 16; off > 0; off >>= 1) {
            v[c] += __shfl_xor_sync(0xffffffffu, v[c], off);
            q[c] += __shfl_xor_sync(0xffffffffu, q[c], off);
        }
    }
    int warp = t >> 5, lane = t & 31;
    if (lane < 16) red[warp][lane] = v[lane];
    else red[warp][lane] = q[lane - 16];
    __syncthreads();
    if (t < 32) {
        float s = 0.f;
#pragma unroll
        for (int wi = 0; wi < 4; wi++) s += red[wi][t];
        int slot = b * 25 + blockIdx.y * 5 + blockIdx.x;
        if (t < 16) ps[(co0 + t) * 64 + slot] = s;
        else pss[(co0 + t - 16) * 64 + slot] = s;
    }
}

// ---------------- BN finalize (50 slots, stride 64) ----------------
__global__ void bn_finalize(const float* __restrict__ ps, const float* __restrict__ pss,
                            const float* __restrict__ g, const float* __restrict__ bb,
                            float* __restrict__ scale, float* __restrict__ shift) {
    int c = threadIdx.x;
    float s = 0.f, ss = 0.f;
#pragma unroll 5
    for (int i = 0; i < 50; i++) { s += ps[c * 64 + i]; ss += pss[c * 64 + i]; }
    float m = s / NHWf;
    float var = ss / NHWf - m * m;
    float rs = rsqrtf(var + EPSV);
    float sc = g[c] * rs;
    scale[c] = sc;
    shift[c] = bb[c] - m * sc;
}

// ---------------- final BN apply (+relu), [c][n] ----------------
__global__ void bn_apply_kernel(const float4* __restrict__ in, float4* __restrict__ out,
                                const float* __restrict__ scale, const float* __restrict__ shift) {
    int i = blockIdx.x * 256 + threadIdx.x;
    int c = (i / 1600) & 63;
    float sc = scale[c], sh = shift[c];
    float4 v = in[i];
    v.x = fmaxf(v.x * sc + sh, 0.f);
    v.y = fmaxf(v.y * sc + sh, 0.f);
    v.z = fmaxf(v.z * sc + sh, 0.f);
    v.w = fmaxf(v.w * sc + sh, 0.f);
    out[i] = v;
}

// ---------------- MEGA projection kernel: all 4 projection families in one launch -------
// grid 1208 x 128 threads. Reads RAW t0T [n][c]; applies BN1 affine+relu inline.
__global__ void __launch_bounds__(128) proj_kernel(
    const float* __restrict__ t0T,
    const float* __restrict__ sc1, const float* __restrict__ sh1,
    const float* __restrict__ cqw, const float* __restrict__ cqb,
    const float* __restrict__ ckw, const float* __restrict__ ckb,
    const float* __restrict__ pqw, const float* __restrict__ pqb,
    const float* __restrict__ pkw, const float* __restrict__ pkb,
    const float* __restrict__ cvw, const float* __restrict__ cvb,
    const float* __restrict__ pvw, const float* __restrict__ pvb,
    float* __restrict__ qb, float* __restrict__ kb,
    __nv_bfloat16* __restrict__ qg, __nv_bfloat16* __restrict__ kg,
    float* __restrict__ vbT, __nv_bfloat16* __restrict__ vg) {
    __shared__ __align__(16) float smem[4224];
    float* aff = smem + 4096;
    int t = threadIdx.x;
    aff[t] = (t < 64) ? sc1[t] : sh1[t - 64];
    const float4* asc4 = (const float4*)aff;
    const float4* ash4 = (const float4*)(aff + 64);
    int a = blockIdx.x;

    if (a < 208) {
        // ---- convqk: q AND k, 8 co each, input read once ----
        int b = a / 104, r = a % 104;
        int co0 = (r / 13) * 8, px = r % 13;
        float* wsmq = smem;
        float* wsmk = smem + 2048;
        for (int i = t; i < 2048; i += 128) {
            int co = i & 7, rr = i >> 3;
            wsmq[rr * 8 + co] = cqw[(co0 + co) * 256 + rr];
            wsmk[rr * 8 + co] = ckw[(co0 + co) * 256 + rr];
        }
        __syncthreads();
        int p = px * 128 + t;
        if (p >= NQ) return;
        int oy = p / 40, ox = p % 40;
        const float* f1b = t0T + (long)b * Nv * 64;
        const float4* p00 = (const float4*)(f1b + ((2 * oy) * Wv + 2 * ox) * 64);
        const float4* p01 = p00 + 16;
        const float4* p10 = (const float4*)(f1b + ((2 * oy + 1) * Wv + 2 * ox) * 64);
        const float4* p11 = p10 + 16;
        ull aq[4], ak[4];
        const ull* w2q = (const ull*)wsmq;
        const ull* w2k = (const ull*)wsmk;
#pragma unroll
        for (int c2 = 0; c2 < 4; c2++) {
            aq[c2] = pk2(cqb[co0 + 2 * c2], cqb[co0 + 2 * c2 + 1]);
            ak[c2] = pk2(ckb[co0 + 2 * c2], ckb[co0 + 2 * c2 + 1]);
        }
#pragma unroll 4
        for (int ci4 = 0; ci4 < 16; ci4++) {
            float4 s4 = asc4[ci4], h4 = ash4[ci4];
            float a0[4], a1[4], a2[4], a3[4];
            *(float4*)a0 = p00[ci4];
            *(float4*)a1 = p01[ci4];
            *(float4*)a2 = p10[ci4];
            *(float4*)a3 = p11[ci4];
            affrelu4(a0, s4, h4);
            affrelu4(a1, s4, h4);
            affrelu4(a2, s4, h4);
            affrelu4(a3, s4, h4);
#pragma unroll
            for (int j = 0; j < 4; j++) {
                ull x0 = pk2(a0[j], a0[j]), x1 = pk2(a1[j], a1[j]);
                ull x2 = pk2(a2[j], a2[j]), x3 = pk2(a3[j], a3[j]);
                int ci = ci4 * 4 + j;
                const ull* wrq = w2q + ci * 16;
                const ull* wrk = w2k + ci * 16;
#pragma unroll
                for (int c2 = 0; c2 < 4; c2++) {
                    ull e = fma2_(x0, wrq[c2], aq[c2]);
                    e = fma2_(x1, wrq[4 + c2], e);
                    e = fma2_(x2, wrq[8 + c2], e);
                    aq[c2] = fma2_(x3, wrq[12 + c2], e);
                    ull f = fma2_(x0, wrk[c2], ak[c2]);
                    f = fma2_(x1, wrk[4 + c2], f);
                    f = fma2_(x2, wrk[8 + c2], f);
                    ak[c2] = fma2_(x3, wrk[12 + c2], f);
                }
            }
        }
        long obase = ((long)b * 64 + co0) * NQ + p;
#pragma unroll
        for (int c2 = 0; c2 < 4; c2++) {
            float lo, hi;
            upk2(aq[c2], lo, hi);
            qb[obase + (long)(2 * c2) * NQ] = lo;
            qb[obase + (long)(2 * c2 + 1) * NQ] = hi;
            upk2(ak[c2], lo, hi);
            kb[obase + (long)(2 * c2) * NQ] = lo;
            kb[obase + (long)(2 * c2 + 1) * NQ] = hi;
        }
    } else if (a < 408) {
        // ---- pq/pk 1x1 conv (8 outs) -> bf16 [n][16] ----
        int id = a - 208;
        int which = id / 100, r2 = id % 100;
        int b = r2 / 50, ny = r2 % 50;
        const float* w = which ? pkw : pqw;
        const float* bias = which ? pkb : pqb;
        __nv_bfloat16* outg = which ? kg : qg;
        float osc = which ? 1.f : L2E;
        float* wsm = smem;
        for (int i = t; i < 512; i += 128) {
            int co = i >> 6, ci = i & 63;
            wsm[ci * 8 + co] = w[i];
        }
        __syncthreads();
        int n = ny * 128 + t;
        float acc[8];
#pragma unroll
        for (int j = 0; j < 8; j++) acc[j] = bias[j];
        const float4* inp = (const float4*)(t0T + ((long)b * Nv + n) * 64);
        const float4* w4p = (const float4*)wsm;
#pragma unroll 4
        for (int ci4 = 0; ci4 < 16; ci4++) {
            float va[4];
            *(float4*)va = inp[ci4];
            affrelu4(va, asc4[ci4], ash4[ci4]);
#pragma unroll
            for (int j = 0; j < 4; j++) {
                float xv = va[j];
                int ci = ci4 * 4 + j;
#pragma unroll
                for (int c4 = 0; c4 < 2; c4++) {
                    float4 w4 = w4p[ci * 2 + c4];
                    acc[c4 * 4 + 0] += w4.x * xv; acc[c4 * 4 + 1] += w4.y * xv;
                    acc[c4 * 4 + 2] += w4.z * xv; acc[c4 * 4 + 3] += w4.w * xv;
                }
            }
        }
        uint4* qd = (uint4*)(outg + ((long)b * Nv + n) * 16);
        qd[0] = make_uint4(pkbf(acc[0] * osc, acc[1] * osc), pkbf(acc[2] * osc, acc[3] * osc),
                           pkbf(acc[4] * osc, acc[5] * osc), pkbf(acc[6] * osc, acc[7] * osc));
        qd[1] = make_uint4(0u, 0u, 0u, 0u);
    } else {
        // ---- cv (-> vbT f32 [n][c]) / pv (-> vg bf16 [c][n]), 16-co groups ----
        int id = a - 408;
        int which = id / 400;
        id -= which * 400;
        int z = id / 100, r2 = id % 100;
        int b = r2 / 50, ny = r2 % 50;
        int co0 = z * 16;
        const float* w = which ? pvw : cvw;
        const float* bias = which ? pvb : cvb;
        float* wsm = smem;
        for (int i = t; i < 1024; i += 128) {
            int co = i >> 6, ci = i & 63;
            wsm[ci * 16 + co] = w[(co0 + co) * 64 + ci];
        }
        __syncthreads();
        int n = ny * 128 + t;
        float acc[16];
#pragma unroll
        for (int co = 0; co < 16; co++) acc[co] = bias[co0 + co];
        const float4* inp = (const float4*)(t0T + ((long)b * Nv + n) * 64);
        const float4* wsm4 = (const float4*)wsm;
#pragma unroll 4
        for (int ci4 = 0; ci4 < 16; ci4++) {
            float va[4];
            *(float4*)va = inp[ci4];
            affrelu4(va, asc4[ci4], ash4[ci4]);
#pragma unroll
            for (int j = 0; j < 4; j++) {
                float xv = va[j];
#pragma unroll
                for (int c4 = 0; c4 < 4; c4++) {
                    float4 w4 = wsm4[(ci4 * 4 + j) * 4 + c4];
                    acc[c4 * 4 + 0] += w4.x * xv;
                    acc[c4 * 4 + 1] += w4.y * xv;
                    acc[c4 * 4 + 2] += w4.z * xv;
                    acc[c4 * 4 + 3] += w4.w * xv;
                }
            }
        }
        if (which == 0) {
            float4* ob = (float4*)(vbT + ((long)b * Nv + n) * 64 + co0);
#pragma unroll
            for (int c4 = 0; c4 < 4; c4++)
                ob[c4] = make_float4(acc[4 * c4], acc[4 * c4 + 1], acc[4 * c4 + 2],
                                     acc[4 * c4 + 3]);
        } else {
            __nv_bfloat16* ob = vg + ((long)b * 64 + co0) * Nv + n;
#pragma unroll
            for (int co = 0; co < 16; co++) ob[(long)co * Nv] = __float2bfloat16(acc[co]);
        }
    }
}

// ---------------- conv1x1 from [n][c] input, 16-co groups (sab only) -------------------
__global__ void conv1x1T_kernel(const float* __restrict__ inT, const float* __restrict__ w,
                                float* __restrict__ out) {
    __shared__ __align__(16) float wsm[1024];
    int b = blockIdx.x;
    int co0 = blockIdx.z * 16;
    int n = blockIdx.y * 128 + threadIdx.x;
    const float* wb = w + (long)b * 4096;
    for (int i = threadIdx.x; i < 1024; i += 128) {
        int co = i >> 6, ci = i & 63;
        wsm[ci * 16 + co] = wb[(co0 + co) * 64 + ci];
    }
    __syncthreads();
    float acc[16];
#pragma unroll
    for (int co = 0; co < 16; co++) acc[co] = 0.f;
    const float4* inp = (const float4*)(inT + ((long)b * Nv + n) * 64);
    const float4* wsm4 = (const float4*)wsm;
#pragma unroll 4
    for (int ci4 = 0; ci4 < 16; ci4++) {
        float va[4];
        *(float4*)va = inp[ci4];
#pragma unroll
        for (int j = 0; j < 4; j++) {
            float xv = va[j];
#pragma unroll
            for (int c4 = 0; c4 < 4; c4++) {
                float4 w4 = wsm4[(ci4 * 4 + j) * 4 + c4];
                acc[c4 * 4 + 0] += w4.x * xv;
                acc[c4 * 4 + 1] += w4.y * xv;
                acc[c4 * 4 + 2] += w4.z * xv;
                acc[c4 * 4 + 3] += w4.w * xv;
            }
        }
    }
    float* ob = out + ((long)b * 64 + co0) * Nv + n;
#pragma unroll
    for (int co = 0; co < 16; co++) ob[(long)co * Nv] = acc[co];
}

// ---------------- CAM energy + softmax, 512 threads (8 slices x 64 rows) ----------------
__global__ void __launch_bounds__(512) cam_kernel(const float* __restrict__ q,
                                                  const float* __restrict__ k,
                                                  float* __restrict__ attn) {
    __shared__ __align__(16) float qsm[NQ];
    __shared__ float part[512];
    __shared__ float er[64];
    __shared__ float pe[64];
    int b = blockIdx.x >> 6, c = blockIdx.x & 63;
    const float* qr = q + (long)(b * 64 + c) * NQ;
    if (threadIdx.x < 400)
        ((float4*)qsm)[threadIdx.x] = ((const float4*)qr)[threadIdx.x];
    __syncthreads();
    int d = threadIdx.x & 63;
    int slice = threadIdx.x >> 6;  // 0..7, 50 float4 each
    const float4* kr = (const float4*)(k + (long)(b * 64 + d) * NQ) + slice * 50;
    const float4* q4 = (const float4*)qsm + slice * 50;
    float s = 0.f;
#pragma unroll 10
    for (int i = 0; i < 50; i++) {
        float4 kv = kr[i];
        float4 qv = q4[i];
        s += qv.x * kv.x + qv.y * kv.y + qv.z * kv.z + qv.w * kv.w;
    }
    part[slice * 64 + d] = s;
    __syncthreads();
    if (threadIdx.x < 64) {
        int dd = threadIdx.x;
        float e = 0.f;
#pragma unroll
        for (int sl = 0; sl < 8; sl++) e += part[sl * 64 + dd];
        er[dd] = e;
    }
    __syncthreads();
    if (threadIdx.x < 64) {
        int dd = threadIdx.x;
        float e = er[dd];
        float mn = er[0];
        for (int i = 1; i < 64; i++) mn = fminf(mn, er[i]);
        pe[dd] = __expf(mn - e);
    }
    __syncthreads();
    if (threadIdx.x < 64) {
        int dd = threadIdx.x;
        float sum = 0.f;
        for (int i = 0; i < 64; i++) sum += pe[i];
        attn[(long)(b * 64 + c) * 64 + dd] = pe[dd] / sum;
    }
}

// ---------------- PAM: flash attention via mma.sync bf16, 128-key tiles ----------------
__global__ void __launch_bounds__(128) pam_mma_kernel(
    const __nv_bfloat16* __restrict__ qg, const __nv_bfloat16* __restrict__ kg,
    const __nv_bfloat16* __restrict__ vg, float* __restrict__ sc) {
    __shared__ __align__(16) __nv_bfloat16 Qs[64 * 16];
    __shared__ __align__(16) __nv_bfloat16 Ks[128 * 16];
    __shared__ __align__(16) __nv_bfloat16 Vs[64 * 136];
    int b = blockIdx.y;
    int q0 = blockIdx.x * 64;
    int t = threadIdx.x, w = t >> 5, lane = t & 31;
    int g = lane >> 2, ti = lane & 3;

    ((uint4*)Qs)[t] = ((const uint4*)(qg + ((long)b * Nv + q0) * 16))[t];
    __syncthreads();

    unsigned qa0, qa1, qa2, qa3;
    {
        const unsigned* qw = (const unsigned*)Qs;
        int r = w * 16 + g;
        qa0 = qw[r * 8 + ti];
        qa1 = qw[(r + 8) * 8 + ti];
        qa2 = qw[r * 8 + ti + 4];
        qa3 = qw[(r + 8) * 8 + ti + 4];
    }

    float o[8][4];
#pragma unroll
    for (int nc = 0; nc < 8; nc++) { o[nc][0] = o[nc][1] = o[nc][2] = o[nc][3] = 0.f; }
    float li_lo = 0.f, li_hi = 0.f, mi_lo = -1e30f, mi_hi = -1e30f;

    for (int j0 = 0; j0 < Nv; j0 += 128) {
        __syncthreads();
        {
            const uint4* src = (const uint4*)(kg + ((long)b * Nv + j0) * 16);
            ((uint4*)Ks)[t] = src[t];
            ((uint4*)Ks)[t + 128] = src[t + 128];
        }
#pragma unroll
        for (int i = t; i < 1024; i += 128) {
            int c = i >> 4, h = i & 15;
            *(uint4*)(Vs + c * 136 + h * 8) =
                *(const uint4*)(vg + ((long)(b * 64 + c)) * Nv + j0 + h * 8);
        }
        __syncthreads();

#pragma unroll
        for (int sub = 0; sub < 2; sub++) {
            float s[8][4];
            const unsigned* kw = (const unsigned*)Ks + sub * 512;
#pragma unroll
            for (int nt = 0; nt < 8; nt++) {
                int j = nt * 8 + g;
                unsigned b0 = kw[j * 8 + ti];
                unsigned b1 = kw[j * 8 + ti + 4];
                s[nt][0] = s[nt][1] = s[nt][2] = s[nt][3] = 0.f;
                mma16816(s[nt], qa0, qa1, qa2, qa3, b0, b1);
            }
            float mlo = s[0][0], mhi = s[0][2];
#pragma unroll
            for (int nt = 0; nt < 8; nt++) {
                mlo = fmaxf(mlo, fmaxf(s[nt][0], s[nt][1]));
                mhi = fmaxf(mhi, fmaxf(s[nt][2], s[nt][3]));
            }
            mlo = fmaxf(mlo, __shfl_xor_sync(0xffffffffu, mlo, 1));
            mlo = fmaxf(mlo, __shfl_xor_sync(0xffffffffu, mlo, 2));
            mhi = fmaxf(mhi, __shfl_xor_sync(0xffffffffu, mhi, 1));
            mhi = fmaxf(mhi, __shfl_xor_sync(0xffffffffu, mhi, 2));
            float nmlo = fmaxf(mi_lo, mlo), nmhi = fmaxf(mi_hi, mhi);
            float clo = ex2_(mi_lo - nmlo), chi = ex2_(mi_hi - nmhi);
            li_lo *= clo; li_hi *= chi;
#pragma unroll
            for (int nc = 0; nc < 8; nc++) {
                o[nc][0] *= clo; o[nc][1] *= clo; o[nc][2] *= chi; o[nc][3] *= chi;
            }
            unsigned pa[8][2];
#pragma unroll
            for (int nt = 0; nt < 8; nt++) {
                float p0 = ex2_(s[nt][0] - nmlo);
                float p1 = ex2_(s[nt][1] - nmlo);
                float p2 = ex2_(s[nt][2] - nmhi);
                float p3 = ex2_(s[nt][3] - nmhi);
                li_lo += p0 + p1;
                li_hi += p2 + p3;
                pa[nt][0] = pkbf(p0, p1);
                pa[nt][1] = pkbf(p2, p3);
            }
            mi_lo = nmlo; mi_hi = nmhi;

            const unsigned* vw = (const unsigned*)Vs + sub * 32;
#pragma unroll
            for (int nc = 0; nc < 8; nc++) {
                int c = nc * 8 + g;
                const unsigned* vr = vw + c * 68 + ti;
#pragma unroll
                for (int i = 0; i < 4; i++) {
                    unsigned b0 = vr[8 * i];
                    unsigned b1 = vr[8 * i + 4];
                    mma16816(o[nc], pa[2 * i][0], pa[2 * i][1],
                             pa[2 * i + 1][0], pa[2 * i + 1][1], b0, b1);
                }
            }
        }
    }
    li_lo += __shfl_xor_sync(0xffffffffu, li_lo, 1);
    li_lo += __shfl_xor_sync(0xffffffffu, li_lo, 2);
    li_hi += __shfl_xor_sync(0xffffffffu, li_hi, 1);
    li_hi += __shfl_xor_sync(0xffffffffu, li_hi, 2);
    float inv_lo = 1.f / li_lo, inv_hi = 1.f / li_hi;
    int q = q0 + w * 16 + g;
#pragma unroll
    for (int nc = 0; nc < 8; nc++) {
        int c = nc * 8 + ti * 2;
        sc[((long)(b * 64 + c)) * Nv + q] = o[nc][0] * inv_lo;
        sc[((long)(b * 64 + c + 1)) * Nv + q] = o[nc][1] * inv_lo;
        sc[((long)(b * 64 + c)) * Nv + q + 8] = o[nc][2] * inv_hi;
        sc[((long)(b * 64 + c + 1)) * Nv + q + 8] = o[nc][3] * inv_hi;
    }
}

// ---------------- feat_sum (BN1 affine-relu on raw t0) + BN2 stats (2-slot stride) -----
__global__ void fsum_kernel(const float* __restrict__ sa, const float* __restrict__ sc,
                            const float* __restrict__ f1raw,
                            const float* __restrict__ sc1, const float* __restrict__ sh1,
                            const float* __restrict__ gamma1, const float* __restrict__ gamma2,
                            float* __restrict__ out,
                            float* __restrict__ ps2, float* __restrict__ pss2) {
    __shared__ float r1[256], r2[256];
    int bz = blockIdx.x;
    int b = bz >> 6, c = bz & 63;
    float g1 = gamma1[0], g2 = gamma2[0];
    float s1 = sc1[c], h1 = sh1[c];
    long base = (long)bz * Nv;
    const float4* sa4 = (const float4*)(sa + base);
    const float4* sc4 = (const float4*)(sc + base);
    const float4* f4 = (const float4*)(f1raw + base);
    float4* o4 = (float4*)(out + base);
    float s = 0.f, ss = 0.f;
    for (int i = threadIdx.x; i < 1600; i += 256) {
        float4 a = sa4[i], bb = sc4[i], f = f4[i];
        float4 v;
        v.x = g1 * a.x + g2 * bb.x + fmaxf(f.x * s1 + h1, 0.f);
        v.y = g1 * a.y + g2 * bb.y + fmaxf(f.y * s1 + h1, 0.f);
        v.z = g1 * a.z + g2 * bb.z + fmaxf(f.z * s1 + h1, 0.f);
        v.w = g1 * a.w + g2 * bb.w + fmaxf(f.w * s1 + h1, 0.f);
        o4[i] = v;
        s += v.x + v.y + v.z + v.w;
        ss += v.x * v.x + v.y * v.y + v.z * v.z + v.w * v.w;
    }
    int t = threadIdx.x;
    r1[t] = s; r2[t] = ss;
    __syncthreads();
    for (int st = 128; st > 0; st >>= 1) {
        if (t < st) { r1[t] += r1[t + st]; r2[t] += r2[t + st]; }
        __syncthreads();
    }
    if (t == 0) { ps2[c * 2 + b] = r1[0]; pss2[c * 2 + b] = r2[0]; }
}

// ---------------- host launch ----------------
extern "C" void kernel_launch(void* const* d_in, const int* in_sizes, int n_in,
                              void* d_out, int out_size) {
    const float* x     = (const float*)d_in[0];
    const float* Wc    = (const float*)d_in[1];
    const float* bn1g  = (const float*)d_in[2];
    const float* bn1b  = (const float*)d_in[3];
    const float* cqw   = (const float*)d_in[4];
    const float* cqb   = (const float*)d_in[5];
    const float* ckw   = (const float*)d_in[6];
    const float* ckb   = (const float*)d_in[7];
    const float* cvw   = (const float*)d_in[8];
    const float* cvb   = (const float*)d_in[9];
    const float* pqw   = (const float*)d_in[10];
    const float* pqb   = (const float*)d_in[11];
    const float* pkw   = (const float*)d_in[12];
    const float* pkb   = (const float*)d_in[13];
    const float* pvw   = (const float*)d_in[14];
    const float* pvb   = (const float*)d_in[15];
    const float* gamma1= (const float*)d_in[16];
    const float* gamma2= (const float*)d_in[17];
    const float* bn2g  = (const float*)d_in[18];
    const float* bn2b  = (const float*)d_in[19];
    const float* Wd    = (const float*)d_in[20];
    const float* bn3g  = (const float*)d_in[21];
    const float* bn3b  = (const float*)d_in[22];

    float* base = nullptr;
    cudaGetSymbolAddress((void**)&base, g_buf);
    float* t0    = base + OFF_T0;
    float* t0T   = base + OFF_T0T;
    float* t1    = base + OFF_T1;
    float* vbT   = base + OFF_VBT;
    float* sab   = base + OFF_SAB;
    float* scb   = base + OFF_SCB;
    float* qb    = base + OFF_QB;
    float* kb    = base + OFF_KB;
    float* attn  = base + OFF_ATTN;
    float* ps    = base + OFF_PS;
    float* pss   = base + OFF_PSS;
    float* ps2   = base + OFF_PS2;
    float* pss2  = base + OFF_PSS2;
    float* sc1   = base + OFF_SC1;
    float* sh1   = base + OFF_SH1;
    __nv_bfloat16* qg = (__nv_bfloat16*)(base + OFF_QG);
    __nv_bfloat16* kg = (__nv_bfloat16*)(base + OFF_KG);
    __nv_bfloat16* vg = (__nv_bfloat16*)(base + OFF_VG);

    const int C3SMEM = 32 * 324 * 4 + 64 * 9 * 8 * 8;  // 78336
    cudaFuncSetAttribute(conv3x3_kernel<0, 1>, cudaFuncAttributeMaxDynamicSharedMemorySize,
                         C3SMEM);
    cudaFuncSetAttribute(conv3x3_kernel<1, 0>, cudaFuncAttributeMaxDynamicSharedMemorySize,
                         C3SMEM);

    dim3 cgrid(5, 5, Bv * 4), cblk(16, 8);

    // 1-2: conv_c (+raw T output, +BN1 stats) -> BN1 finalize
    conv3x3_kernel<0, 1><<<cgrid, cblk, C3SMEM>>>(x, Wc, nullptr, nullptr, nullptr, nullptr,
                                                  t0, t0T, ps, pss);
    bn_finalize<<<1, 64>>>(ps, pss, bn1g, bn1b, sc1, sh1);

    // 3: all projections in one launch (BN1 affine-relu inline)
    proj_kernel<<<1208, 128>>>(t0T, sc1, sh1, cqw, cqb, ckw, ckb, pqw, pqb, pkw, pkb,
                               cvw, cvb, pvw, pvb, qb, kb, qg, kg, vbT, vg);

    // 4-5: CAM
    cam_kernel<<<Bv * Cv, 512>>>(qb, kb, attn);
    conv1x1T_kernel<<<dim3(Bv, 50, 4), 128>>>(vbT, attn, sab);

    // 6: PAM
    pam_mma_kernel<<<dim3(100, Bv), 128>>>(qg, kg, vg, scb);

    // 7-10: combine -> conv_d (BN2 affine in-kernel, +BN3 stats) -> finalize -> apply
    fsum_kernel<<<Bv * Cv, 256>>>(sab, scb, t0, sc1, sh1, gamma1, gamma2, t0, ps2, pss2);
    conv3x3_kernel<1, 0><<<cgrid, cblk, C3SMEM>>>(t0, Wd, ps2, pss2, bn2g, bn2b,
                                                  t1, nullptr, ps, pss);
    bn_finalize<<<1, 64>>>(ps, pss, bn3g, bn3b, sc1, sh1);
    bn_apply_kernel<<<800, 256>>>((const float4*)t1, (float4*)d_out, sc1, sh1);
}

// round 15
// speedup vs baseline: 1.0988x; 1.0154x over previous
#include <cuda_runtime.h>
#include <cuda_bf16.h>
#include <math.h>

#define Bv 2
#define Cv 64
#define Hv 80
#define Wv 80
#define Nv 6400
#define NQ 1600
#define NHWf 12800.0f
#define EPSV 1e-5f
#define L2E 1.44269504088896f

typedef unsigned long long ull;

// ---------------- packed helpers ----------------
__device__ __forceinline__ ull pk2(float lo, float hi) {
    ull r; asm("mov.b64 %0,{%1,%2};" : "=l"(r) : "f"(lo), "f"(hi)); return r;
}
__device__ __forceinline__ void upk2(ull v, float& lo, float& hi) {
    asm("mov.b64 {%0,%1},%2;" : "=f"(lo), "=f"(hi) : "l"(v));
}
__device__ __forceinline__ ull fma2_(ull a, ull b, ull c) {
    ull d; asm("fma.rn.f32x2 %0,%1,%2,%3;" : "=l"(d) : "l"(a), "l"(b), "l"(c)); return d;
}
__device__ __forceinline__ float ex2_(float x) {
    float y; asm("ex2.approx.ftz.f32 %0,%1;" : "=f"(y) : "f"(x)); return y;
}
__device__ __forceinline__ unsigned pkbf(float lo, float hi) {
    unsigned d; asm("cvt.rn.bf16x2.f32 %0,%1,%2;" : "=r"(d) : "f"(hi), "f"(lo)); return d;
}
__device__ __forceinline__ void mma16816(float* c, unsigned a0, unsigned a1, unsigned a2,
                                         unsigned a3, unsigned b0, unsigned b1) {
    asm("mma.sync.aligned.m16n8k16.row.col.f32.bf16.bf16.f32 "
        "{%0,%1,%2,%3},{%4,%5,%6,%7},{%8,%9},{%0,%1,%2,%3};"
        : "+f"(c[0]), "+f"(c[1]), "+f"(c[2]), "+f"(c[3])
        : "r"(a0), "r"(a1), "r"(a2), "r"(a3), "r"(b0), "r"(b1));
}
__device__ __forceinline__ void affrelu4(float* v, float4 s, float4 h) {
    v[0] = fmaxf(v[0] * s.x + h.x, 0.f);
    v[1] = fmaxf(v[1] * s.y + h.y, 0.f);
    v[2] = fmaxf(v[2] * s.z + h.z, 0.f);
    v[3] = fmaxf(v[3] * s.w + h.w, 0.f);
}

// ---------------- scratch ----------------
#define OFF_T0     0
#define OFF_T0T    (OFF_T0   + Bv*Cv*Nv)   /* [b][n][c] transposed (raw, pre-BN) */
#define OFF_T1     (OFF_T0T  + Bv*Cv*Nv)
#define OFF_VBT    (OFF_T1   + Bv*Cv*Nv)   /* [b][n][c] */
#define OFF_SAB    (OFF_VBT  + Bv*Cv*Nv)
#define OFF_SCB    (OFF_SAB  + Bv*Cv*Nv)
#define OFF_QB     (OFF_SCB  + Bv*Cv*Nv)
#define OFF_KB     (OFF_QB   + Bv*Cv*NQ)
#define OFF_ATTN   (OFF_KB   + Bv*Cv*NQ)
#define OFF_PS     (OFF_ATTN + Bv*Cv*Cv)
#define OFF_PSS    (OFF_PS   + 64*64)
#define OFF_PS2    (OFF_PSS  + 64*64)
#define OFF_PSS2   (OFF_PS2  + 128)
#define OFF_SC1    (OFF_PSS2 + 128)
#define OFF_SH1    (OFF_SC1  + 64)
#define OFF_QG     (OFF_SH1  + 64)          /* bf16 [B][N][16] */
#define OFF_KG     (OFF_QG   + Bv*Nv*8)
#define OFF_VG     (OFF_KG   + Bv*Nv*8)     /* bf16 [B][C][N] */
#define BUF_TOTAL  (OFF_VG   + Bv*Cv*Nv/2)

__device__ __align__(16) float g_buf[BUF_TOTAL];

// ---------------- conv3x3 (pad=1, no bias) + fused per-block BN stats ------------------
// grid (5,5, B*4), block (16,8) — each thread computes 2 pixels x 16 co.
// AFFINE: input BN affine computed in-kernel from psIn/pssIn (2 slots, stride 2) + g/bb.
template <int AFFINE, int WRITET>
__global__ void conv3x3_kernel(const float* __restrict__ in, const float* __restrict__ w,
                               const float* __restrict__ psIn, const float* __restrict__ pssIn,
                               const float* __restrict__ bng, const float* __restrict__ bnb,
                               float* __restrict__ out, float* __restrict__ outT,
                               float* __restrict__ ps, float* __restrict__ pss) {
    extern __shared__ float sm[];
    float* tile = sm;                                   // 32*324
    ull* w2 = (ull*)(sm + 32 * 324);                    // [ci*9+tap][8] co-pairs (all 64 ci)
    __shared__ float aff[128];
    __shared__ float red[4][32];
    int bz = blockIdx.z;
    int b = bz >> 2, co0 = (bz & 3) * 16;
    int t = threadIdx.y * 16 + threadIdx.x;             // 0..127

    float* wflat = (float*)w2;
    for (int i = t; i < 9216; i += 128) {
        int co = i & 15, r = i >> 4;
        wflat[r * 16 + co] = w[(co0 + co) * 576 + r];
    }
    if (AFFINE && t < 64) {
        float s = psIn[t * 2] + psIn[t * 2 + 1];
        float ss = pssIn[t * 2] + pssIn[t * 2 + 1];
        float m = s / NHWf;
        float var = ss / NHWf - m * m;
        float rs = rsqrtf(var + EPSV);
        float sc = bng[t] * rs;
        aff[t] = sc;
        aff[64 + t] = bnb[t] - m * sc;
    }

    int oy0 = blockIdx.y * 16, ox0 = blockIdx.x * 16;
    const float* inb = in + (long)b * Cv * Nv;

    ull acc0[8], acc1[8];
#pragma unroll
    for (int c2 = 0; c2 < 8; c2++) { acc0[c2] = pk2(0.f, 0.f); acc1[c2] = pk2(0.f, 0.f); }

    for (int chunk = 0; chunk < 2; chunk++) {
        int cbase = chunk * 32;
        __syncthreads();
        for (int i = t; i < 32 * 324; i += 128) {
            int ci = i / 324;
            int pos = i - ci * 324;
            int r = pos / 18, c2 = pos - r * 18;
            int gy = oy0 + r - 1, gx = ox0 + c2 - 1;
            float v = 0.f;
            if (gy >= 0 && gy < Hv && gx >= 0 && gx < Wv) {
                v = inb[(cbase + ci) * Nv + gy * Wv + gx];
                if (AFFINE) v = v * aff[cbase + ci] + aff[64 + cbase + ci];
            }
            tile[i] = v;
        }
        __syncthreads();

        for (int ci = 0; ci < 32; ci++) {
            const float* tp0 = tile + ci * 324 + threadIdx.y * 18 + threadIdx.x;
            const float* tp1 = tp0 + 8 * 18;
            float x0[9], x1[9];
#pragma unroll
            for (int ky = 0; ky < 3; ky++)
#pragma unroll
                for (int kx = 0; kx < 3; kx++) {
                    x0[ky * 3 + kx] = tp0[ky * 18 + kx];
                    x1[ky * 3 + kx] = tp1[ky * 18 + kx];
                }
            const ull* wr = w2 + (long)(cbase + ci) * 72;
#pragma unroll
            for (int tap = 0; tap < 9; tap++) {
                ull xd0 = pk2(x0[tap], x0[tap]);
                ull xd1 = pk2(x1[tap], x1[tap]);
#pragma unroll
                for (int c2 = 0; c2 < 8; c2++) {
                    ull wv = wr[tap * 8 + c2];
                    acc0[c2] = fma2_(xd0, wv, acc0[c2]);
                    acc1[c2] = fma2_(xd1, wv, acc1[c2]);
                }
            }
        }
    }
    int pix0 = (oy0 + threadIdx.y) * Wv + ox0 + threadIdx.x;
    int pix1 = pix0 + 8 * Wv;
    long ob0 = ((long)b * 64 + co0) * Nv + pix0;
    long ob1 = ((long)b * 64 + co0) * Nv + pix1;
    float v[16], q[16], va[16], vb2[16];
#pragma unroll
    for (int c2 = 0; c2 < 8; c2++) {
        float lo0, hi0, lo1, hi1;
        upk2(acc0[c2], lo0, hi0);
        upk2(acc1[c2], lo1, hi1);
        out[ob0 + (long)(2 * c2) * Nv] = lo0;
        out[ob0 + (long)(2 * c2 + 1) * Nv] = hi0;
        out[ob1 + (long)(2 * c2) * Nv] = lo1;
        out[ob1 + (long)(2 * c2 + 1) * Nv] = hi1;
        va[2 * c2] = lo0; va[2 * c2 + 1] = hi0;
        vb2[2 * c2] = lo1; vb2[2 * c2 + 1] = hi1;
        v[2 * c2] = lo0 + lo1; v[2 * c2 + 1] = hi0 + hi1;
        q[2 * c2] = lo0 * lo0 + lo1 * lo1; q[2 * c2 + 1] = hi0 * hi0 + hi1 * hi1;
    }
    if (WRITET) {
        float4* t0p = (float4*)(outT + ((long)b * Nv + pix0) * 64 + co0);
        float4* t1p = (float4*)(outT + ((long)b * Nv + pix1) * 64 + co0);
#pragma unroll
        for (int c4 = 0; c4 < 4; c4++) {
            t0p[c4] = make_float4(va[4 * c4], va[4 * c4 + 1], va[4 * c4 + 2], va[4 * c4 + 3]);
            t1p[c4] = make_float4(vb2[4 * c4], vb2[4 * c4 + 1], vb2[4 * c4 + 2], vb2[4 * c4 + 3]);
        }
    }
#pragma unroll
    for (int c = 0; c < 16; c++) {
#pragma unroll
        for (int off = 16; off > 0; off >>= 1) {
            v[c] += __shfl_xor_sync(0xffffffffu, v[c], off);
            q[c] += __shfl_xor_sync(0xffffffffu, q[c], off);
        }
    }
    int warp = t >> 5, lane = t & 31;
    if (lane < 16) red[warp][lane] = v[lane];
    else red[warp][lane] = q[lane - 16];
    __syncthreads();
    if (t < 32) {
        float s = 0.f;
#pragma unroll
        for (int wi = 0; wi < 4; wi++) s += red[wi][t];
        int slot = b * 25 + blockIdx.y * 5 + blockIdx.x;
        if (t < 16) ps[(co0 + t) * 64 + slot] = s;
        else pss[(co0 + t - 16) * 64 + slot] = s;
    }
}

// ---------------- BN finalize (50 slots, stride 64) ----------------
__global__ void bn_finalize(const float* __restrict__ ps, const float* __restrict__ pss,
                            const float* __restrict__ g, const float* __restrict__ bb,
                            float* __restrict__ scale, float* __restrict__ shift) {
    int c = threadIdx.x;
    float s = 0.f, ss = 0.f;
#pragma unroll 5
    for (int i = 0; i < 50; i++) { s += ps[c * 64 + i]; ss += pss[c * 64 + i]; }
    float m = s / NHWf;
    float var = ss / NHWf - m * m;
    float rs = rsqrtf(var + EPSV);
    float sc = g[c] * rs;
    scale[c] = sc;
    shift[c] = bb[c] - m * sc;
}

// ---------------- final BN apply (+relu), [c][n] ----------------
__global__ void bn_apply_kernel(const float4* __restrict__ in, float4* __restrict__ out,
                                const float* __restrict__ scale, const float* __restrict__ shift) {
    int i = blockIdx.x * 256 + threadIdx.x;
    int c = (i / 1600) & 63;
    float sc = scale[c], sh = shift[c];
    float4 v = in[i];
    v.x = fmaxf(v.x * sc + sh, 0.f);
    v.y = fmaxf(v.y * sc + sh, 0.f);
    v.z = fmaxf(v.z * sc + sh, 0.f);
    v.w = fmaxf(v.w * sc + sh, 0.f);
    out[i] = v;
}

// ---------------- MEGA projection kernel: all 4 projection families in one launch -------
// grid 1208 x 128 threads. Reads RAW t0T [n][c]; applies BN1 affine+relu inline.
__global__ void __launch_bounds__(128) proj_kernel(
    const float* __restrict__ t0T,
    const float* __restrict__ sc1, const float* __restrict__ sh1,
    const float* __restrict__ cqw, const float* __restrict__ cqb,
    const float* __restrict__ ckw, const float* __restrict__ ckb,
    const float* __restrict__ pqw, const float* __restrict__ pqb,
    const float* __restrict__ pkw, const float* __restrict__ pkb,
    const float* __restrict__ cvw, const float* __restrict__ cvb,
    const float* __restrict__ pvw, const float* __restrict__ pvb,
    float* __restrict__ qb, float* __restrict__ kb,
    __nv_bfloat16* __restrict__ qg, __nv_bfloat16* __restrict__ kg,
    float* __restrict__ vbT, __nv_bfloat16* __restrict__ vg) {
    __shared__ __align__(16) float smem[4224];
    float* aff = smem + 4096;
    int t = threadIdx.x;
    aff[t] = (t < 64) ? sc1[t] : sh1[t - 64];
    const float4* asc4 = (const float4*)aff;
    const float4* ash4 = (const float4*)(aff + 64);
    int a = blockIdx.x;

    if (a < 208) {
        // ---- convqk: q AND k, 8 co each, input read once ----
        int b = a / 104, r = a % 104;
        int co0 = (r / 13) * 8, px = r % 13;
        float* wsmq = smem;
        float* wsmk = smem + 2048;
        for (int i = t; i < 2048; i += 128) {
            int co = i & 7, rr = i >> 3;
            wsmq[rr * 8 + co] = cqw[(co0 + co) * 256 + rr];
            wsmk[rr * 8 + co] = ckw[(co0 + co) * 256 + rr];
        }
        __syncthreads();
        int p = px * 128 + t;
        if (p >= NQ) return;
        int oy = p / 40, ox = p % 40;
        const float* f1b = t0T + (long)b * Nv * 64;
        const float4* p00 = (const float4*)(f1b + ((2 * oy) * Wv + 2 * ox) * 64);
        const float4* p01 = p00 + 16;
        const float4* p10 = (const float4*)(f1b + ((2 * oy + 1) * Wv + 2 * ox) * 64);
        const float4* p11 = p10 + 16;
        ull aq[4], ak[4];
        const ull* w2q = (const ull*)wsmq;
        const ull* w2k = (const ull*)wsmk;
#pragma unroll
        for (int c2 = 0; c2 < 4; c2++) {
            aq[c2] = pk2(cqb[co0 + 2 * c2], cqb[co0 + 2 * c2 + 1]);
            ak[c2] = pk2(ckb[co0 + 2 * c2], ckb[co0 + 2 * c2 + 1]);
        }
#pragma unroll 4
        for (int ci4 = 0; ci4 < 16; ci4++) {
            float4 s4 = asc4[ci4], h4 = ash4[ci4];
            float a0[4], a1[4], a2[4], a3[4];
            *(float4*)a0 = p00[ci4];
            *(float4*)a1 = p01[ci4];
            *(float4*)a2 = p10[ci4];
            *(float4*)a3 = p11[ci4];
            affrelu4(a0, s4, h4);
            affrelu4(a1, s4, h4);
            affrelu4(a2, s4, h4);
            affrelu4(a3, s4, h4);
#pragma unroll
            for (int j = 0; j < 4; j++) {
                ull x0 = pk2(a0[j], a0[j]), x1 = pk2(a1[j], a1[j]);
                ull x2 = pk2(a2[j], a2[j]), x3 = pk2(a3[j], a3[j]);
                int ci = ci4 * 4 + j;
                const ull* wrq = w2q + ci * 16;
                const ull* wrk = w2k + ci * 16;
#pragma unroll
                for (int c2 = 0; c2 < 4; c2++) {
                    ull e = fma2_(x0, wrq[c2], aq[c2]);
                    e = fma2_(x1, wrq[4 + c2], e);
                    e = fma2_(x2, wrq[8 + c2], e);
                    aq[c2] = fma2_(x3, wrq[12 + c2], e);
                    ull f = fma2_(x0, wrk[c2], ak[c2]);
                    f = fma2_(x1, wrk[4 + c2], f);
                    f = fma2_(x2, wrk[8 + c2], f);
                    ak[c2] = fma2_(x3, wrk[12 + c2], f);
                }
            }
        }
        long obase = ((long)b * 64 + co0) * NQ + p;
#pragma unroll
        for (int c2 = 0; c2 < 4; c2++) {
            float lo, hi;
            upk2(aq[c2], lo, hi);
            qb[obase + (long)(2 * c2) * NQ] = lo;
            qb[obase + (long)(2 * c2 + 1) * NQ] = hi;
            upk2(ak[c2], lo, hi);
            kb[obase + (long)(2 * c2) * NQ] = lo;
            kb[obase + (long)(2 * c2 + 1) * NQ] = hi;
        }
    } else if (a < 408) {
        // ---- pq/pk 1x1 conv (8 outs) -> bf16 [n][16] ----
        int id = a - 208;
        int which = id / 100, r2 = id % 100;
        int b = r2 / 50, ny = r2 % 50;
        const float* w = which ? pkw : pqw;
        const float* bias = which ? pkb : pqb;
        __nv_bfloat16* outg = which ? kg : qg;
        float osc = which ? 1.f : L2E;
        float* wsm = smem;
        for (int i = t; i < 512; i += 128) {
            int co = i >> 6, ci = i & 63;
            wsm[ci * 8 + co] = w[i];
        }
        __syncthreads();
        int n = ny * 128 + t;
        float acc[8];
#pragma unroll
        for (int j = 0; j < 8; j++) acc[j] = bias[j];
        const float4* inp = (const float4*)(t0T + ((long)b * Nv + n) * 64);
        const float4* w4p = (const float4*)wsm;
#pragma unroll 4
        for (int ci4 = 0; ci4 < 16; ci4++) {
            float va[4];
            *(float4*)va = inp[ci4];
            affrelu4(va, asc4[ci4], ash4[ci4]);
#pragma unroll
            for (int j = 0; j < 4; j++) {
                float xv = va[j];
                int ci = ci4 * 4 + j;
#pragma unroll
                for (int c4 = 0; c4 < 2; c4++) {
                    float4 w4 = w4p[ci * 2 + c4];
                    acc[c4 * 4 + 0] += w4.x * xv; acc[c4 * 4 + 1] += w4.y * xv;
                    acc[c4 * 4 + 2] += w4.z * xv; acc[c4 * 4 + 3] += w4.w * xv;
                }
            }
        }
        uint4* qd = (uint4*)(outg + ((long)b * Nv + n) * 16);
        qd[0] = make_uint4(pkbf(acc[0] * osc, acc[1] * osc), pkbf(acc[2] * osc, acc[3] * osc),
                           pkbf(acc[4] * osc, acc[5] * osc), pkbf(acc[6] * osc, acc[7] * osc));
        qd[1] = make_uint4(0u, 0u, 0u, 0u);
    } else {
        // ---- cv (-> vbT f32 [n][c]) / pv (-> vg bf16 [c][n]), 16-co groups ----
        int id = a - 408;
        int which = id / 400;
        id -= which * 400;
        int z = id / 100, r2 = id % 100;
        int b = r2 / 50, ny = r2 % 50;
        int co0 = z * 16;
        const float* w = which ? pvw : cvw;
        const float* bias = which ? pvb : cvb;
        float* wsm = smem;
        for (int i = t; i < 1024; i += 128) {
            int co = i >> 6, ci = i & 63;
            wsm[ci * 16 + co] = w[(co0 + co) * 64 + ci];
        }
        __syncthreads();
        int n = ny * 128 + t;
        float acc[16];
#pragma unroll
        for (int co = 0; co < 16; co++) acc[co] = bias[co0 + co];
        const float4* inp = (const float4*)(t0T + ((long)b * Nv + n) * 64);
        const float4* wsm4 = (const float4*)wsm;
#pragma unroll 4
        for (int ci4 = 0; ci4 < 16; ci4++) {
            float va[4];
            *(float4*)va = inp[ci4];
            affrelu4(va, asc4[ci4], ash4[ci4]);
#pragma unroll
            for (int j = 0; j < 4; j++) {
                float xv = va[j];
#pragma unroll
                for (int c4 = 0; c4 < 4; c4++) {
                    float4 w4 = wsm4[(ci4 * 4 + j) * 4 + c4];
                    acc[c4 * 4 + 0] += w4.x * xv;
                    acc[c4 * 4 + 1] += w4.y * xv;
                    acc[c4 * 4 + 2] += w4.z * xv;
                    acc[c4 * 4 + 3] += w4.w * xv;
                }
            }
        }
        if (which == 0) {
            float4* ob = (float4*)(vbT + ((long)b * Nv + n) * 64 + co0);
#pragma unroll
            for (int c4 = 0; c4 < 4; c4++)
                ob[c4] = make_float4(acc[4 * c4], acc[4 * c4 + 1], acc[4 * c4 + 2],
                                     acc[4 * c4 + 3]);
        } else {
            __nv_bfloat16* ob = vg + ((long)b * 64 + co0) * Nv + n;
#pragma unroll
            for (int co = 0; co < 16; co++) ob[(long)co * Nv] = __float2bfloat16(acc[co]);
        }
    }
}

// ---------------- conv1x1 from [n][c] input, 16-co groups (sab only) -------------------
__global__ void conv1x1T_kernel(const float* __restrict__ inT, const float* __restrict__ w,
                                float* __restrict__ out) {
    __shared__ __align__(16) float wsm[1024];
    int b = blockIdx.x;
    int co0 = blockIdx.z * 16;
    int n = blockIdx.y * 128 + threadIdx.x;
    const float* wb = w + (long)b * 4096;
    for (int i = threadIdx.x; i < 1024; i += 128) {
        int co = i >> 6, ci = i & 63;
        wsm[ci * 16 + co] = wb[(co0 + co) * 64 + ci];
    }
    __syncthreads();
    float acc[16];
#pragma unroll
    for (int co = 0; co < 16; co++) acc[co] = 0.f;
    const float4* inp = (const float4*)(inT + ((long)b * Nv + n) * 64);
    const float4* wsm4 = (const float4*)wsm;
#pragma unroll 4
    for (int ci4 = 0; ci4 < 16; ci4++) {
        float va[4];
        *(float4*)va = inp[ci4];
#pragma unroll
        for (int j = 0; j < 4; j++) {
            float xv = va[j];
#pragma unroll
            for (int c4 = 0; c4 < 4; c4++) {
                float4 w4 = wsm4[(ci4 * 4 + j) * 4 + c4];
                acc[c4 * 4 + 0] += w4.x * xv;
                acc[c4 * 4 + 1] += w4.y * xv;
                acc[c4 * 4 + 2] += w4.z * xv;
                acc[c4 * 4 + 3] += w4.w * xv;
            }
        }
    }
    float* ob = out + ((long)b * 64 + co0) * Nv + n;
#pragma unroll
    for (int co = 0; co < 16; co++) ob[(long)co * Nv] = acc[co];
}

// ---------------- CAM energy + softmax: warp-per-4-rows, coalesced K reads --------------
// grid (B*64), block 512 (16 warps). Warp w computes energies for d = w*4..w*4+3.
__global__ void __launch_bounds__(512) cam_kernel(const float* __restrict__ q,
                                                  const float* __restrict__ k,
                                                  float* __restrict__ attn) {
    __shared__ __align__(16) float qsm[NQ];
    __shared__ float er[64];
    __shared__ float pe[64];
    int b = blockIdx.x >> 6, c = blockIdx.x & 63;
    const float* qr = q + (long)(b * 64 + c) * NQ;
    if (threadIdx.x < 400)
        ((float4*)qsm)[threadIdx.x] = ((const float4*)qr)[threadIdx.x];
    __syncthreads();
    int warp = threadIdx.x >> 5, lane = threadIdx.x & 31;
    const float4* q4 = (const float4*)qsm;
#pragma unroll
    for (int r = 0; r < 4; r++) {
        int d = warp * 4 + r;
        const float4* kr = (const float4*)(k + (long)(b * 64 + d) * NQ);
        float s = 0.f;
#pragma unroll 4
        for (int i = lane; i < 400; i += 32) {
            float4 kv = kr[i];
            float4 qv = q4[i];
            s += qv.x * kv.x + qv.y * kv.y + qv.z * kv.z + qv.w * kv.w;
        }
#pragma unroll
        for (int off = 16; off > 0; off >>= 1)
            s += __shfl_xor_sync(0xffffffffu, s, off);
        if (lane == 0) er[d] = s;
    }
    __syncthreads();
    if (threadIdx.x < 64) {
        int dd = threadIdx.x;
        float e = er[dd];
        float mn = er[0];
        for (int i = 1; i < 64; i++) mn = fminf(mn, er[i]);
        pe[dd] = __expf(mn - e);
    }
    __syncthreads();
    if (threadIdx.x < 64) {
        int dd = threadIdx.x;
        float sum = 0.f;
        for (int i = 0; i < 64; i++) sum += pe[i];
        attn[(long)(b * 64 + c) * 64 + dd] = pe[dd] / sum;
    }
}

// ---------------- PAM: flash attention via mma.sync bf16, 128-key tiles ----------------
__global__ void __launch_bounds__(128) pam_mma_kernel(
    const __nv_bfloat16* __restrict__ qg, const __nv_bfloat16* __restrict__ kg,
    const __nv_bfloat16* __restrict__ vg, float* __restrict__ sc) {
    __shared__ __align__(16) __nv_bfloat16 Qs[64 * 16];
    __shared__ __align__(16) __nv_bfloat16 Ks[128 * 16];
    __shared__ __align__(16) __nv_bfloat16 Vs[64 * 136];
    int b = blockIdx.y;
    int q0 = blockIdx.x * 64;
    int t = threadIdx.x, w = t >> 5, lane = t & 31;
    int g = lane >> 2, ti = lane & 3;

    ((uint4*)Qs)[t] = ((const uint4*)(qg + ((long)b * Nv + q0) * 16))[t];
    __syncthreads();

    unsigned qa0, qa1, qa2, qa3;
    {
        const unsigned* qw = (const unsigned*)Qs;
        int r = w * 16 + g;
        qa0 = qw[r * 8 + ti];
        qa1 = qw[(r + 8) * 8 + ti];
        qa2 = qw[r * 8 + ti + 4];
        qa3 = qw[(r + 8) * 8 + ti + 4];
    }

    float o[8][4];
#pragma unroll
    for (int nc = 0; nc < 8; nc++) { o[nc][0] = o[nc][1] = o[nc][2] = o[nc][3] = 0.f; }
    float li_lo = 0.f, li_hi = 0.f, mi_lo = -1e30f, mi_hi = -1e30f;

    for (int j0 = 0; j0 < Nv; j0 += 128) {
        __syncthreads();
        {
            const uint4* src = (const uint4*)(kg + ((long)b * Nv + j0) * 16);
            ((uint4*)Ks)[t] = src[t];
            ((uint4*)Ks)[t + 128] = src[t + 128];
        }
#pragma unroll
        for (int i = t; i < 1024; i += 128) {
            int c = i >> 4, h = i & 15;
            *(uint4*)(Vs + c * 136 + h * 8) =
                *(const uint4*)(vg + ((long)(b * 64 + c)) * Nv + j0 + h * 8);
        }
        __syncthreads();

#pragma unroll
        for (int sub = 0; sub < 2; sub++) {
            float s[8][4];
            const unsigned* kw = (const unsigned*)Ks + sub * 512;
#pragma unroll
            for (int nt = 0; nt < 8; nt++) {
                int j = nt * 8 + g;
                unsigned b0 = kw[j * 8 + ti];
                unsigned b1 = kw[j * 8 + ti + 4];
                s[nt][0] = s[nt][1] = s[nt][2] = s[nt][3] = 0.f;
                mma16816(s[nt], qa0, qa1, qa2, qa3, b0, b1);
            }
            float mlo = s[0][0], mhi = s[0][2];
#pragma unroll
            for (int nt = 0; nt < 8; nt++) {
                mlo = fmaxf(mlo, fmaxf(s[nt][0], s[nt][1]));
                mhi = fmaxf(mhi, fmaxf(s[nt][2], s[nt][3]));
            }
            mlo = fmaxf(mlo, __shfl_xor_sync(0xffffffffu, mlo, 1));
            mlo = fmaxf(mlo, __shfl_xor_sync(0xffffffffu, mlo, 2));
            mhi = fmaxf(mhi, __shfl_xor_sync(0xffffffffu, mhi, 1));
            mhi = fmaxf(mhi, __shfl_xor_sync(0xffffffffu, mhi, 2));
            float nmlo = fmaxf(mi_lo, mlo), nmhi = fmaxf(mi_hi, mhi);
            float clo = ex2_(mi_lo - nmlo), chi = ex2_(mi_hi - nmhi);
            li_lo *= clo; li_hi *= chi;
#pragma unroll
            for (int nc = 0; nc < 8; nc++) {
                o[nc][0] *= clo; o[nc][1] *= clo; o[nc][2] *= chi; o[nc][3] *= chi;
            }
            unsigned pa[8][2];
#pragma unroll
            for (int nt = 0; nt < 8; nt++) {
                float p0 = ex2_(s[nt][0] - nmlo);
                float p1 = ex2_(s[nt][1] - nmlo);
                float p2 = ex2_(s[nt][2] - nmhi);
                float p3 = ex2_(s[nt][3] - nmhi);
                li_lo += p0 + p1;
                li_hi += p2 + p3;
                pa[nt][0] = pkbf(p0, p1);
                pa[nt][1] = pkbf(p2, p3);
            }
            mi_lo = nmlo; mi_hi = nmhi;

            const unsigned* vw = (const unsigned*)Vs + sub * 32;
#pragma unroll
            for (int nc = 0; nc < 8; nc++) {
                int c = nc * 8 + g;
                const unsigned* vr = vw + c * 68 + ti;
#pragma unroll
                for (int i = 0; i < 4; i++) {
                    unsigned b0 = vr[8 * i];
                    unsigned b1 = vr[8 * i + 4];
                    mma16816(o[nc], pa[2 * i][0], pa[2 * i][1],
                             pa[2 * i + 1][0], pa[2 * i + 1][1], b0, b1);
                }
            }
        }
    }
    li_lo += __shfl_xor_sync(0xffffffffu, li_lo, 1);
    li_lo += __shfl_xor_sync(0xffffffffu, li_lo, 2);
    li_hi += __shfl_xor_sync(0xffffffffu, li_hi, 1);
    li_hi += __shfl_xor_sync(0xffffffffu, li_hi, 2);
    float inv_lo = 1.f / li_lo, inv_hi = 1.f / li_hi;
    int q = q0 + w * 16 + g;
#pragma unroll
    for (int nc = 0; nc < 8; nc++) {
        int c = nc * 8 + ti * 2;
        sc[((long)(b * 64 + c)) * Nv + q] = o[nc][0] * inv_lo;
        sc[((long)(b * 64 + c + 1)) * Nv + q] = o[nc][1] * inv_lo;
        sc[((long)(b * 64 + c)) * Nv + q + 8] = o[nc][2] * inv_hi;
        sc[((long)(b * 64 + c + 1)) * Nv + q + 8] = o[nc][3] * inv_hi;
    }
}

// ---------------- feat_sum (BN1 affine-relu on raw t0) + BN2 stats (2-slot stride) -----
__global__ void fsum_kernel(const float* __restrict__ sa, const float* __restrict__ sc,
                            const float* __restrict__ f1raw,
                            const float* __restrict__ sc1, const float* __restrict__ sh1,
                            const float* __restrict__ gamma1, const float* __restrict__ gamma2,
                            float* __restrict__ out,
                            float* __restrict__ ps2, float* __restrict__ pss2) {
    __shared__ float r1[256], r2[256];
    int bz = blockIdx.x;
    int b = bz >> 6, c = bz & 63;
    float g1 = gamma1[0], g2 = gamma2[0];
    float s1 = sc1[c], h1 = sh1[c];
    long base = (long)bz * Nv;
    const float4* sa4 = (const float4*)(sa + base);
    const float4* sc4 = (const float4*)(sc + base);
    const float4* f4 = (const float4*)(f1raw + base);
    float4* o4 = (float4*)(out + base);
    float s = 0.f, ss = 0.f;
    for (int i = threadIdx.x; i < 1600; i += 256) {
        float4 a = sa4[i], bb = sc4[i], f = f4[i];
        float4 v;
        v.x = g1 * a.x + g2 * bb.x + fmaxf(f.x * s1 + h1, 0.f);
        v.y = g1 * a.y + g2 * bb.y + fmaxf(f.y * s1 + h1, 0.f);
        v.z = g1 * a.z + g2 * bb.z + fmaxf(f.z * s1 + h1, 0.f);
        v.w = g1 * a.w + g2 * bb.w + fmaxf(f.w * s1 + h1, 0.f);
        o4[i] = v;
        s += v.x + v.y + v.z + v.w;
        ss += v.x * v.x + v.y * v.y + v.z * v.z + v.w * v.w;
    }
    int t = threadIdx.x;
    r1[t] = s; r2[t] = ss;
    __syncthreads();
    for (int st = 128; st > 0; st >>= 1) {
        if (t < st) { r1[t] += r1[t + st]; r2[t] += r2[t + st]; }
        __syncthreads();
    }
    if (t == 0) { ps2[c * 2 + b] = r1[0]; pss2[c * 2 + b] = r2[0]; }
}

// ---------------- host launch ----------------
extern "C" void kernel_launch(void* const* d_in, const int* in_sizes, int n_in,
                              void* d_out, int out_size) {
    const float* x     = (const float*)d_in[0];
    const float* Wc    = (const float*)d_in[1];
    const float* bn1g  = (const float*)d_in[2];
    const float* bn1b  = (const float*)d_in[3];
    const float* cqw   = (const float*)d_in[4];
    const float* cqb   = (const float*)d_in[5];
    const float* ckw   = (const float*)d_in[6];
    const float* ckb   = (const float*)d_in[7];
    const float* cvw   = (const float*)d_in[8];
    const float* cvb   = (const float*)d_in[9];
    const float* pqw   = (const float*)d_in[10];
    const float* pqb   = (const float*)d_in[11];
    const float* pkw   = (const float*)d_in[12];
    const float* pkb   = (const float*)d_in[13];
    const float* pvw   = (const float*)d_in[14];
    const float* pvb   = (const float*)d_in[15];
    const float* gamma1= (const float*)d_in[16];
    const float* gamma2= (const float*)d_in[17];
    const float* bn2g  = (const float*)d_in[18];
    const float* bn2b  = (const float*)d_in[19];
    const float* Wd    = (const float*)d_in[20];
    const float* bn3g  = (const float*)d_in[21];
    const float* bn3b  = (const float*)d_in[22];

    float* base = nullptr;
    cudaGetSymbolAddress((void**)&base, g_buf);
    float* t0    = base + OFF_T0;
    float* t0T   = base + OFF_T0T;
    float* t1    = base + OFF_T1;
    float* vbT   = base + OFF_VBT;
    float* sab   = base + OFF_SAB;
    float* scb   = base + OFF_SCB;
    float* qb    = base + OFF_QB;
    float* kb    = base + OFF_KB;
    float* attn  = base + OFF_ATTN;
    float* ps    = base + OFF_PS;
    float* pss   = base + OFF_PSS;
    float* ps2   = base + OFF_PS2;
    float* pss2  = base + OFF_PSS2;
    float* sc1   = base + OFF_SC1;
    float* sh1   = base + OFF_SH1;
    __nv_bfloat16* qg = (__nv_bfloat16*)(base + OFF_QG);
    __nv_bfloat16* kg = (__nv_bfloat16*)(base + OFF_KG);
    __nv_bfloat16* vg = (__nv_bfloat16*)(base + OFF_VG);

    const int C3SMEM = 32 * 324 * 4 + 64 * 9 * 8 * 8;  // 78336
    cudaFuncSetAttribute(conv3x3_kernel<0, 1>, cudaFuncAttributeMaxDynamicSharedMemorySize,
                         C3SMEM);
    cudaFuncSetAttribute(conv3x3_kernel<1, 0>, cudaFuncAttributeMaxDynamicSharedMemorySize,
                         C3SMEM);

    dim3 cgrid(5, 5, Bv * 4), cblk(16, 8);

    // 1-2: conv_c (+raw T output, +BN1 stats) -> BN1 finalize
    conv3x3_kernel<0, 1><<<cgrid, cblk, C3SMEM>>>(x, Wc, nullptr, nullptr, nullptr, nullptr,
                                                  t0, t0T, ps, pss);
    bn_finalize<<<1, 64>>>(ps, pss, bn1g, bn1b, sc1, sh1);

    // 3: all projections in one launch (BN1 affine-relu inline)
    proj_kernel<<<1208, 128>>>(t0T, sc1, sh1, cqw, cqb, ckw, ckb, pqw, pqb, pkw, pkb,
                               cvw, cvb, pvw, pvb, qb, kb, qg, kg, vbT, vg);

    // 4-5: CAM
    cam_kernel<<<Bv * Cv, 512>>>(qb, kb, attn);
    conv1x1T_kernel<<<dim3(Bv, 50, 4), 128>>>(vbT, attn, sab);

    // 6: PAM
    pam_mma_kernel<<<dim3(100, Bv), 128>>>(qg, kg, vg, scb);

    // 7-10: combine -> conv_d (BN2 affine in-kernel, +BN3 stats) -> finalize -> apply
    fsum_kernel<<<Bv * Cv, 256>>>(sab, scb, t0, sc1, sh1, gamma1, gamma2, t0, ps2, pss2);
    conv3x3_kernel<1, 0><<<cgrid, cblk, C3SMEM>>>(t0, Wd, ps2, pss2, bn2g, bn2b,
                                                  t1, nullptr, ps, pss);
    bn_finalize<<<1, 64>>>(ps, pss, bn3g, bn3b, sc1, sh1);
    bn_apply_kernel<<<800, 256>>>((const float4*)t1, (float4*)d_out, sc1, sh1);
}